// round 2
// baseline (speedup 1.0000x reference)
#include <cuda_runtime.h>
#include <math.h>

// Problem constants
#define BT_    16          // B*T
#define NH_    8           // heads
#define HD_    64          // head dim
#define HH_    32          // spatial H
#define WW_    32          // spatial W
#define SEQ_   1024        // HH*WW
#define NTOK_  16384       // BT*SEQ
#define DIM_   512
#define INNER_ 512         // NH*HD
#define QKVN_  1536

#define PI_F 3.14159265358979323846f

// Scratch (device globals: allocation-free per harness rules)
__device__ float g_qkv[(size_t)NTOK_ * QKVN_];    // 96 MB
__device__ float g_attn[(size_t)NTOK_ * INNER_];  // 32 MB

// ---------------------------------------------------------------------------
// SGEMM: C[M,N] = A[M,K] * B[N,K]^T (+ bias[N] if bias != nullptr)
// 128x128 block tile, K-tile 8, 256 threads, 8x8 register micro-tile.
// M,N multiples of 128, K multiple of 8.
// ---------------------------------------------------------------------------
__global__ __launch_bounds__(256) void sgemm_nt(
    const float* __restrict__ A, const float* __restrict__ B,
    const float* __restrict__ bias, float* __restrict__ C,
    int M, int N, int K)
{
    __shared__ float As[8][128];
    __shared__ float Bs[8][128];

    const int bm = blockIdx.y * 128;
    const int bn = blockIdx.x * 128;
    const int tid = threadIdx.x;
    const int tx = tid & 15;       // 0..15 -> 8 cols each
    const int ty = tid >> 4;       // 0..15 -> 8 rows each

    const int lrow = tid >> 1;          // 0..127
    const int lq   = (tid & 1) << 2;    // 0 or 4

    const float* Ap = A + (size_t)(bm + lrow) * K + lq;
    const float* Bp = B + (size_t)(bn + lrow) * K + lq;

    float acc[8][8];
#pragma unroll
    for (int i = 0; i < 8; i++)
#pragma unroll
        for (int j = 0; j < 8; j++) acc[i][j] = 0.0f;

    for (int k0 = 0; k0 < K; k0 += 8) {
        float4 a4 = *reinterpret_cast<const float4*>(Ap + k0);
        float4 b4 = *reinterpret_cast<const float4*>(Bp + k0);
        __syncthreads();
        As[lq + 0][lrow] = a4.x; As[lq + 1][lrow] = a4.y;
        As[lq + 2][lrow] = a4.z; As[lq + 3][lrow] = a4.w;
        Bs[lq + 0][lrow] = b4.x; Bs[lq + 1][lrow] = b4.y;
        Bs[lq + 2][lrow] = b4.z; Bs[lq + 3][lrow] = b4.w;
        __syncthreads();
#pragma unroll
        for (int k = 0; k < 8; k++) {
            float4 a0 = *reinterpret_cast<const float4*>(&As[k][ty * 8]);
            float4 a1 = *reinterpret_cast<const float4*>(&As[k][ty * 8 + 4]);
            float4 b0 = *reinterpret_cast<const float4*>(&Bs[k][tx * 8]);
            float4 b1 = *reinterpret_cast<const float4*>(&Bs[k][tx * 8 + 4]);
            float ra[8] = {a0.x, a0.y, a0.z, a0.w, a1.x, a1.y, a1.z, a1.w};
            float rb[8] = {b0.x, b0.y, b0.z, b0.w, b1.x, b1.y, b1.z, b1.w};
#pragma unroll
            for (int i = 0; i < 8; i++)
#pragma unroll
                for (int j = 0; j < 8; j++)
                    acc[i][j] += ra[i] * rb[j];
        }
    }

    // Epilogue
    float bz[8];
#pragma unroll
    for (int j = 0; j < 8; j++)
        bz[j] = bias ? bias[bn + tx * 8 + j] : 0.0f;

#pragma unroll
    for (int i = 0; i < 8; i++) {
        size_t row = (size_t)(bm + ty * 8 + i);
        float4 o0 = make_float4(acc[i][0] + bz[0], acc[i][1] + bz[1],
                                acc[i][2] + bz[2], acc[i][3] + bz[3]);
        float4 o1 = make_float4(acc[i][4] + bz[4], acc[i][5] + bz[5],
                                acc[i][6] + bz[6], acc[i][7] + bz[7]);
        *reinterpret_cast<float4*>(&C[row * N + bn + tx * 8]) = o0;
        *reinterpret_cast<float4*>(&C[row * N + bn + tx * 8 + 4]) = o1;
    }
}

// ---------------------------------------------------------------------------
// Axial RoPE applied in-place to q and k inside g_qkv.
// freqs(i,j,d): pairs p<16 use theta = ph(i)*base[p], p>=16 use pw(j)*base[p-16]
// base[k] = (1 + k*127/15)*pi ; ph(i) = -1 + i*2/31
// out[2p]   = t[2p]*cos - t[2p+1]*sin
// out[2p+1] = t[2p+1]*cos + t[2p]*sin
// ---------------------------------------------------------------------------
__global__ __launch_bounds__(256) void rope_kernel(float* __restrict__ qkv)
{
    int idx = blockIdx.x * blockDim.x + threadIdx.x;
    const int total = NTOK_ * NH_ * 32;  // pairs
    if (idx >= total) return;

    int p   = idx & 31;
    int hh  = (idx >> 5) & 7;
    int tok = idx >> 8;        // / (32*8)
    int sp  = tok & (SEQ_ - 1);
    int i   = sp >> 5;          // row (H)
    int j   = sp & 31;          // col (W)

    float base = (1.0f + (float)(p & 15) * (127.0f / 15.0f)) * PI_F;
    float pos  = (p < 16) ? (-1.0f + (float)i * (2.0f / 31.0f))
                          : (-1.0f + (float)j * (2.0f / 31.0f));
    float th = pos * base;
    float s, c;
    sincosf(th, &s, &c);

    size_t col = (size_t)hh * HD_ + (size_t)p * 2;
    float* q = &qkv[(size_t)tok * QKVN_ + col];
    float* k = q + 512;

    float q0 = q[0], q1 = q[1];
    q[0] = q0 * c - q1 * s;
    q[1] = q1 * c + q0 * s;
    float k0 = k[0], k1 = k[1];
    k[0] = k0 * c - k1 * s;
    k[1] = k1 * c + k0 * s;
}

// ---------------------------------------------------------------------------
// Streaming-softmax attention.
// Grid: (SEQ/32, BT*NH). Block: 256 threads (16x16), micro-tile 2 rows x 4 cols.
// Q tile: 32 queries. KV tiles: 64 keys, 16 tiles.
// smem: sQ [d][qrow] 64x36, sK [d][kcol] 64x68 (reused as P [kcol][qrow] 64x36),
//       sV [kcol][d] 64x68.  Total < 48 KB static.
// ---------------------------------------------------------------------------
__global__ __launch_bounds__(256) void attn_kernel(
    const float* __restrict__ qkv, float* __restrict__ outb)
{
    const int bh = blockIdx.y;
    const int bt = bh >> 3;
    const int h  = bh & 7;
    const int q0 = blockIdx.x * 32;
    const int tid = threadIdx.x;
    const int tx = tid & 15;   // col group: cols tx*4..tx*4+3
    const int ty = tid >> 4;   // row group: rows ty*2, ty*2+1

    __shared__ float sQ[64 * 36];   // [d][qrow]
    __shared__ float sK[64 * 68];   // [d][kcol]; reused as P: [kcol][qrow(36)]
    __shared__ float sV[64 * 68];   // [kcol][d]
    __shared__ float s_m[32], s_l[32], s_al[32];

    float* St = sK;  // P buffer view: St[c*36 + r]

    if (tid < 32) { s_m[tid] = -1e30f; s_l[tid] = 0.0f; }

    // Load Q tile (32 rows x 64 d), stored transposed [d][row]
    const size_t baseQ = ((size_t)bt * SEQ_ + q0) * QKVN_ + (size_t)h * HD_;
#pragma unroll
    for (int it = 0; it < 2; it++) {
        int idx4 = tid + it * 256;        // 0..511
        int row  = idx4 >> 4;             // 0..31
        int d4   = (idx4 & 15) << 2;      // 0..60
        float4 v = *reinterpret_cast<const float4*>(&qkv[baseQ + (size_t)row * QKVN_ + d4]);
        sQ[(d4 + 0) * 36 + row] = v.x;
        sQ[(d4 + 1) * 36 + row] = v.y;
        sQ[(d4 + 2) * 36 + row] = v.z;
        sQ[(d4 + 3) * 36 + row] = v.w;
    }

    float O[2][4] = {{0.f, 0.f, 0.f, 0.f}, {0.f, 0.f, 0.f, 0.f}};

    for (int kt = 0; kt < SEQ_; kt += 64) {
        const size_t baseK = ((size_t)bt * SEQ_ + kt) * QKVN_ + 512 + (size_t)h * HD_;
        const size_t baseV = baseK + 512;

        __syncthreads();  // previous-tile P/V consumers done (also covers Q stores on kt=0)
#pragma unroll
        for (int it = 0; it < 4; it++) {
            int idx4 = tid + it * 256;    // 0..1023
            int row  = idx4 >> 4;         // 0..63
            int d4   = (idx4 & 15) << 2;
            float4 kv = *reinterpret_cast<const float4*>(&qkv[baseK + (size_t)row * QKVN_ + d4]);
            sK[(d4 + 0) * 68 + row] = kv.x;
            sK[(d4 + 1) * 68 + row] = kv.y;
            sK[(d4 + 2) * 68 + row] = kv.z;
            sK[(d4 + 3) * 68 + row] = kv.w;
            float4 vv = *reinterpret_cast<const float4*>(&qkv[baseV + (size_t)row * QKVN_ + d4]);
            *reinterpret_cast<float4*>(&sV[row * 68 + d4]) = vv;
        }
        __syncthreads();

        // S = Q K^T  (2x4 micro-tile)
        float s[2][4] = {{0.f, 0.f, 0.f, 0.f}, {0.f, 0.f, 0.f, 0.f}};
#pragma unroll
        for (int d = 0; d < 64; d++) {
            float2 a = *reinterpret_cast<const float2*>(&sQ[d * 36 + ty * 2]);
            float4 b = *reinterpret_cast<const float4*>(&sK[d * 68 + tx * 4]);
            s[0][0] += a.x * b.x; s[0][1] += a.x * b.y;
            s[0][2] += a.x * b.z; s[0][3] += a.x * b.w;
            s[1][0] += a.y * b.x; s[1][1] += a.y * b.y;
            s[1][2] += a.y * b.z; s[1][3] += a.y * b.w;
        }
        __syncthreads();  // all K reads done before overwriting sK with P

        // write scaled logits transposed: St[col][row]
#pragma unroll
        for (int j = 0; j < 4; j++) {
            St[(tx * 4 + j) * 36 + ty * 2 + 0] = s[0][j] * 0.125f;
            St[(tx * 4 + j) * 36 + ty * 2 + 1] = s[1][j] * 0.125f;
        }
        __syncthreads();

        // Online softmax: one thread per query row
        if (tid < 32) {
            const int r = tid;
            float m_old = s_m[r];
            float mx = m_old;
#pragma unroll 8
            for (int c = 0; c < 64; c++) mx = fmaxf(mx, St[c * 36 + r]);
            float al = __expf(m_old - mx);
            float sum = 0.0f;
#pragma unroll 8
            for (int c = 0; c < 64; c++) {
                float p = __expf(St[c * 36 + r] - mx);
                St[c * 36 + r] = p;
                sum += p;
            }
            s_m[r]  = mx;
            s_l[r]  = s_l[r] * al + sum;
            s_al[r] = al;
        }
        __syncthreads();

        // O = O * alpha + P @ V
        float al0 = s_al[ty * 2 + 0];
        float al1 = s_al[ty * 2 + 1];
#pragma unroll
        for (int j = 0; j < 4; j++) { O[0][j] *= al0; O[1][j] *= al1; }
#pragma unroll
        for (int c = 0; c < 64; c++) {
            float2 p = *reinterpret_cast<const float2*>(&St[c * 36 + ty * 2]);
            float4 v = *reinterpret_cast<const float4*>(&sV[c * 68 + tx * 4]);
            O[0][0] += p.x * v.x; O[0][1] += p.x * v.y;
            O[0][2] += p.x * v.z; O[0][3] += p.x * v.w;
            O[1][0] += p.y * v.x; O[1][1] += p.y * v.y;
            O[1][2] += p.y * v.z; O[1][3] += p.y * v.w;
        }
    }

    // Final normalize + write: attn_out[token, h*64 + d]
    float inv0 = 1.0f / s_l[ty * 2 + 0];
    float inv1 = 1.0f / s_l[ty * 2 + 1];
    const size_t outBase = ((size_t)bt * SEQ_ + q0) * INNER_ + (size_t)h * HD_;
    {
        float4 o0 = make_float4(O[0][0] * inv0, O[0][1] * inv0, O[0][2] * inv0, O[0][3] * inv0);
        float4 o1 = make_float4(O[1][0] * inv1, O[1][1] * inv1, O[1][2] * inv1, O[1][3] * inv1);
        *reinterpret_cast<float4*>(&outb[outBase + (size_t)(ty * 2 + 0) * INNER_ + tx * 4]) = o0;
        *reinterpret_cast<float4*>(&outb[outBase + (size_t)(ty * 2 + 1) * INNER_ + tx * 4]) = o1;
    }
}

// ---------------------------------------------------------------------------
extern "C" void kernel_launch(void* const* d_in, const int* in_sizes, int n_in,
                              void* d_out, int out_size)
{
    const float* x     = (const float*)d_in[0];  // (2,8,32,32,512) = (16384,512)
    const float* w_qkv = (const float*)d_in[1];  // (1536,512)
    const float* w_out = (const float*)d_in[2];  // (512,512)
    const float* b_out = (const float*)d_in[3];  // (512,)
    float* out = (float*)d_out;                  // (16384,512)

    float* qkv = nullptr;
    float* attn = nullptr;
    cudaGetSymbolAddress((void**)&qkv, g_qkv);
    cudaGetSymbolAddress((void**)&attn, g_attn);

    // 1) QKV projection: [16384,512] x [512,1536]^T -> [16384,1536]
    {
        dim3 grid(QKVN_ / 128, NTOK_ / 128);
        sgemm_nt<<<grid, 256>>>(x, w_qkv, nullptr, qkv, NTOK_, QKVN_, DIM_);
    }

    // 2) RoPE on q,k in place
    {
        int total = NTOK_ * NH_ * 32;
        rope_kernel<<<(total + 255) / 256, 256>>>(qkv);
    }

    // 3) Attention (streaming softmax)
    {
        dim3 grid(SEQ_ / 32, BT_ * NH_);
        attn_kernel<<<grid, 256>>>(qkv, attn);
    }

    // 4) Output projection + bias: [16384,512] x [512,512]^T + b
    {
        dim3 grid(INNER_ / 128, NTOK_ / 128);
        sgemm_nt<<<grid, 256>>>(attn, w_out, b_out, out, NTOK_, INNER_, DIM_);
    }
}

// round 3
// speedup vs baseline: 1.4493x; 1.4493x over previous
#include <cuda_runtime.h>
#include <math.h>

// Problem constants
#define BT_    16          // B*T
#define NH_    8           // heads
#define HD_    64          // head dim
#define SEQ_   1024        // 32*32
#define NTOK_  16384       // BT*SEQ
#define DIM_   512
#define INNER_ 512         // NH*HD
#define QKVN_  1536

#define PI_F 3.14159265358979323846f

// Attention tiling
#define BQ_ 128
#define BK_ 64
#define QS_ 132            // sQ stride (floats)
#define KS_ 68             // sK/sV/sP stride (floats)
#define ATTN_SMEM_FLOATS (64*QS_ + 64*KS_ + BK_*KS_ + BQ_*KS_)

// Scratch (device globals: allocation-free per harness rules)
__device__ float g_qkv[(size_t)NTOK_ * QKVN_];    // 96 MB
__device__ float g_attn[(size_t)NTOK_ * INNER_];  // 32 MB

// ---------------------------------------------------------------------------
// SGEMM: C[M,N] = A[M,K] * B[N,K]^T (+ bias[N] if bias != nullptr)
// ---------------------------------------------------------------------------
__global__ __launch_bounds__(256) void sgemm_nt(
    const float* __restrict__ A, const float* __restrict__ B,
    const float* __restrict__ bias, float* __restrict__ C,
    int M, int N, int K)
{
    __shared__ float As[8][128];
    __shared__ float Bs[8][128];

    const int bm = blockIdx.y * 128;
    const int bn = blockIdx.x * 128;
    const int tid = threadIdx.x;
    const int tx = tid & 15;
    const int ty = tid >> 4;

    const int lrow = tid >> 1;
    const int lq   = (tid & 1) << 2;

    const float* Ap = A + (size_t)(bm + lrow) * K + lq;
    const float* Bp = B + (size_t)(bn + lrow) * K + lq;

    float acc[8][8];
#pragma unroll
    for (int i = 0; i < 8; i++)
#pragma unroll
        for (int j = 0; j < 8; j++) acc[i][j] = 0.0f;

    for (int k0 = 0; k0 < K; k0 += 8) {
        float4 a4 = *reinterpret_cast<const float4*>(Ap + k0);
        float4 b4 = *reinterpret_cast<const float4*>(Bp + k0);
        __syncthreads();
        As[lq + 0][lrow] = a4.x; As[lq + 1][lrow] = a4.y;
        As[lq + 2][lrow] = a4.z; As[lq + 3][lrow] = a4.w;
        Bs[lq + 0][lrow] = b4.x; Bs[lq + 1][lrow] = b4.y;
        Bs[lq + 2][lrow] = b4.z; Bs[lq + 3][lrow] = b4.w;
        __syncthreads();
#pragma unroll
        for (int k = 0; k < 8; k++) {
            float4 a0 = *reinterpret_cast<const float4*>(&As[k][ty * 8]);
            float4 a1 = *reinterpret_cast<const float4*>(&As[k][ty * 8 + 4]);
            float4 b0 = *reinterpret_cast<const float4*>(&Bs[k][tx * 8]);
            float4 b1 = *reinterpret_cast<const float4*>(&Bs[k][tx * 8 + 4]);
            float ra[8] = {a0.x, a0.y, a0.z, a0.w, a1.x, a1.y, a1.z, a1.w};
            float rb[8] = {b0.x, b0.y, b0.z, b0.w, b1.x, b1.y, b1.z, b1.w};
#pragma unroll
            for (int i = 0; i < 8; i++)
#pragma unroll
                for (int j = 0; j < 8; j++)
                    acc[i][j] += ra[i] * rb[j];
        }
    }

    float bz[8];
#pragma unroll
    for (int j = 0; j < 8; j++)
        bz[j] = bias ? bias[bn + tx * 8 + j] : 0.0f;

#pragma unroll
    for (int i = 0; i < 8; i++) {
        size_t row = (size_t)(bm + ty * 8 + i);
        float4 o0 = make_float4(acc[i][0] + bz[0], acc[i][1] + bz[1],
                                acc[i][2] + bz[2], acc[i][3] + bz[3]);
        float4 o1 = make_float4(acc[i][4] + bz[4], acc[i][5] + bz[5],
                                acc[i][6] + bz[6], acc[i][7] + bz[7]);
        *reinterpret_cast<float4*>(&C[row * N + bn + tx * 8]) = o0;
        *reinterpret_cast<float4*>(&C[row * N + bn + tx * 8 + 4]) = o1;
    }
}

// ---------------------------------------------------------------------------
// Axial RoPE in-place on q,k of g_qkv.
// ---------------------------------------------------------------------------
__global__ __launch_bounds__(256) void rope_kernel(float* __restrict__ qkv)
{
    int idx = blockIdx.x * blockDim.x + threadIdx.x;
    const int total = NTOK_ * NH_ * 32;
    if (idx >= total) return;

    int p   = idx & 31;
    int hh  = (idx >> 5) & 7;
    int tok = idx >> 8;
    int sp  = tok & (SEQ_ - 1);
    int i   = sp >> 5;
    int j   = sp & 31;

    float base = (1.0f + (float)(p & 15) * (127.0f / 15.0f)) * PI_F;
    float pos  = (p < 16) ? (-1.0f + (float)i * (2.0f / 31.0f))
                          : (-1.0f + (float)j * (2.0f / 31.0f));
    float th = pos * base;
    float s, c;
    sincosf(th, &s, &c);

    size_t col = (size_t)hh * HD_ + (size_t)p * 2;
    float* q = &qkv[(size_t)tok * QKVN_ + col];
    float* k = q + 512;

    float q0 = q[0], q1 = q[1];
    q[0] = q0 * c - q1 * s;
    q[1] = q1 * c + q0 * s;
    float k0 = k[0], k1 = k[1];
    k[0] = k0 * c - k1 * s;
    k[1] = k1 * c + k0 * s;
}

// ---------------------------------------------------------------------------
// Flash attention, fully parallel online softmax in registers.
// Grid: (SEQ/BQ, BT*NH). Block: 256 threads (16x16).
// Thread (tx,ty): rows ty*8+[0..7], cols tx*4+[0..3].
// S kept in registers; row stats via shfl over the 16 lanes sharing ty.
// ---------------------------------------------------------------------------
__global__ __launch_bounds__(256, 2) void attn_kernel(
    const float* __restrict__ qkv, float* __restrict__ outb)
{
    extern __shared__ float smem[];
    float* sQ = smem;                    // [64][QS_]  (d-major, q-row contiguous)
    float* sK = sQ + 64 * QS_;           // [64][KS_]  (d-major, k-col contiguous)
    float* sV = sK + 64 * KS_;           // [BK][KS_]  (row-major)
    float* sP = sV + BK_ * KS_;          // [BQ][KS_]  (row-major)

    const int bh = blockIdx.y;
    const int bt = bh >> 3;
    const int h  = bh & 7;
    const int q0 = blockIdx.x * BQ_;
    const int tid = threadIdx.x;
    const int tx = tid & 15;
    const int ty = tid >> 4;

    // ---- Load Q tile (BQ x 64), transposed into sQ[d][row] ----
    const size_t baseQ = ((size_t)bt * SEQ_ + q0) * QKVN_ + (size_t)h * HD_;
#pragma unroll
    for (int it = 0; it < 8; it++) {
        int idx = tid + it * 256;          // 0..2047
        int row = idx >> 4;                // 0..127
        int d4  = (idx & 15) << 2;         // 0..60
        float4 v = *reinterpret_cast<const float4*>(&qkv[baseQ + (size_t)row * QKVN_ + d4]);
        sQ[(d4 + 0) * QS_ + row] = v.x;
        sQ[(d4 + 1) * QS_ + row] = v.y;
        sQ[(d4 + 2) * QS_ + row] = v.z;
        sQ[(d4 + 3) * QS_ + row] = v.w;
    }

    float O[8][4];
    float m[8], l[8];
#pragma unroll
    for (int i = 0; i < 8; i++) {
        m[i] = -1e30f; l[i] = 0.0f;
#pragma unroll
        for (int j = 0; j < 4; j++) O[i][j] = 0.0f;
    }

    for (int kt = 0; kt < SEQ_; kt += BK_) {
        const size_t baseK = ((size_t)bt * SEQ_ + kt) * QKVN_ + 512 + (size_t)h * HD_;
        const size_t baseV = baseK + 512;

        __syncthreads();   // prior-tile consumers of sK/sV/sP done (covers Q on kt=0)
#pragma unroll
        for (int it = 0; it < 4; it++) {
            int idx = tid + it * 256;      // 0..1023
            int row = idx >> 4;            // 0..63
            int d4  = (idx & 15) << 2;
            float4 kv = *reinterpret_cast<const float4*>(&qkv[baseK + (size_t)row * QKVN_ + d4]);
            sK[(d4 + 0) * KS_ + row] = kv.x;
            sK[(d4 + 1) * KS_ + row] = kv.y;
            sK[(d4 + 2) * KS_ + row] = kv.z;
            sK[(d4 + 3) * KS_ + row] = kv.w;
            float4 vv = *reinterpret_cast<const float4*>(&qkv[baseV + (size_t)row * QKVN_ + d4]);
            *reinterpret_cast<float4*>(&sV[row * KS_ + d4]) = vv;
        }
        __syncthreads();

        // ---- S = Q K^T, 8x4 register tile ----
        float s[8][4];
#pragma unroll
        for (int i = 0; i < 8; i++)
#pragma unroll
            for (int j = 0; j < 4; j++) s[i][j] = 0.0f;

#pragma unroll 4
        for (int d = 0; d < 64; d++) {
            float4 a0 = *reinterpret_cast<const float4*>(&sQ[d * QS_ + ty * 8]);
            float4 a1 = *reinterpret_cast<const float4*>(&sQ[d * QS_ + ty * 8 + 4]);
            float4 b  = *reinterpret_cast<const float4*>(&sK[d * KS_ + tx * 4]);
            float ra[8] = {a0.x, a0.y, a0.z, a0.w, a1.x, a1.y, a1.z, a1.w};
#pragma unroll
            for (int i = 0; i < 8; i++) {
                s[i][0] += ra[i] * b.x;
                s[i][1] += ra[i] * b.y;
                s[i][2] += ra[i] * b.z;
                s[i][3] += ra[i] * b.w;
            }
        }

        // ---- Online softmax (registers + shfl across 16 lanes of same ty) ----
#pragma unroll
        for (int i = 0; i < 8; i++) {
            float s0 = s[i][0] * 0.125f;
            float s1 = s[i][1] * 0.125f;
            float s2 = s[i][2] * 0.125f;
            float s3 = s[i][3] * 0.125f;
            float mx = fmaxf(fmaxf(s0, s1), fmaxf(s2, s3));
#pragma unroll
            for (int off = 8; off > 0; off >>= 1)
                mx = fmaxf(mx, __shfl_xor_sync(0xffffffffu, mx, off));
            float mnew  = fmaxf(m[i], mx);
            float alpha = __expf(m[i] - mnew);
            s0 = __expf(s0 - mnew);
            s1 = __expf(s1 - mnew);
            s2 = __expf(s2 - mnew);
            s3 = __expf(s3 - mnew);
            float sum = (s0 + s1) + (s2 + s3);
#pragma unroll
            for (int off = 8; off > 0; off >>= 1)
                sum += __shfl_xor_sync(0xffffffffu, sum, off);
            l[i] = l[i] * alpha + sum;
            m[i] = mnew;
            O[i][0] *= alpha; O[i][1] *= alpha; O[i][2] *= alpha; O[i][3] *= alpha;
            *reinterpret_cast<float4*>(&sP[(ty * 8 + i) * KS_ + tx * 4]) =
                make_float4(s0, s1, s2, s3);
        }
        __syncthreads();

        // ---- O += P @ V ----
#pragma unroll 4
        for (int c0 = 0; c0 < BK_; c0 += 4) {
            float4 v0 = *reinterpret_cast<const float4*>(&sV[(c0 + 0) * KS_ + tx * 4]);
            float4 v1 = *reinterpret_cast<const float4*>(&sV[(c0 + 1) * KS_ + tx * 4]);
            float4 v2 = *reinterpret_cast<const float4*>(&sV[(c0 + 2) * KS_ + tx * 4]);
            float4 v3 = *reinterpret_cast<const float4*>(&sV[(c0 + 3) * KS_ + tx * 4]);
#pragma unroll
            for (int i = 0; i < 8; i++) {
                float4 p = *reinterpret_cast<const float4*>(&sP[(ty * 8 + i) * KS_ + c0]);
                O[i][0] += p.x * v0.x + p.y * v1.x + p.z * v2.x + p.w * v3.x;
                O[i][1] += p.x * v0.y + p.y * v1.y + p.z * v2.y + p.w * v3.y;
                O[i][2] += p.x * v0.z + p.y * v1.z + p.z * v2.z + p.w * v3.z;
                O[i][3] += p.x * v0.w + p.y * v1.w + p.z * v2.w + p.w * v3.w;
            }
        }
    }

    // ---- Normalize + write ----
    const size_t outBase = ((size_t)bt * SEQ_ + q0) * INNER_ + (size_t)h * HD_;
#pragma unroll
    for (int i = 0; i < 8; i++) {
        float inv = 1.0f / l[i];
        float4 o = make_float4(O[i][0] * inv, O[i][1] * inv, O[i][2] * inv, O[i][3] * inv);
        *reinterpret_cast<float4*>(&outb[outBase + (size_t)(ty * 8 + i) * INNER_ + tx * 4]) = o;
    }
}

// ---------------------------------------------------------------------------
extern "C" void kernel_launch(void* const* d_in, const int* in_sizes, int n_in,
                              void* d_out, int out_size)
{
    const float* x     = (const float*)d_in[0];
    const float* w_qkv = (const float*)d_in[1];
    const float* w_out = (const float*)d_in[2];
    const float* b_out = (const float*)d_in[3];
    float* out = (float*)d_out;

    float* qkv = nullptr;
    float* attn = nullptr;
    cudaGetSymbolAddress((void**)&qkv, g_qkv);
    cudaGetSymbolAddress((void**)&attn, g_attn);

    // 1) QKV projection
    {
        dim3 grid(QKVN_ / 128, NTOK_ / 128);
        sgemm_nt<<<grid, 256>>>(x, w_qkv, nullptr, qkv, NTOK_, QKVN_, DIM_);
    }

    // 2) RoPE
    {
        int total = NTOK_ * NH_ * 32;
        rope_kernel<<<(total + 255) / 256, 256>>>(qkv);
    }

    // 3) Attention
    {
        const int smem_bytes = ATTN_SMEM_FLOATS * (int)sizeof(float);
        static bool attr_set = false;
        if (!attr_set) {
            cudaFuncSetAttribute(attn_kernel,
                                 cudaFuncAttributeMaxDynamicSharedMemorySize, smem_bytes);
            attr_set = true;
        }
        dim3 grid(SEQ_ / BQ_, BT_ * NH_);
        attn_kernel<<<grid, 256, smem_bytes>>>(qkv, attn);
    }

    // 4) Output projection + bias
    {
        dim3 grid(INNER_ / 128, NTOK_ / 128);
        sgemm_nt<<<grid, 256>>>(attn, w_out, b_out, out, NTOK_, INNER_, DIM_);
    }
}

// round 5
// speedup vs baseline: 1.8969x; 1.3088x over previous
#include <cuda_runtime.h>
#include <math.h>
#include <stdint.h>

// Problem constants
#define BT_    16
#define NH_    8
#define HD_    64
#define SEQ_   1024
#define NTOK_  16384
#define DIM_   512
#define INNER_ 512
#define QKVN_  1536
#define GK_    512

#define PI_F 3.14159265358979323846f

// Attention tiling
#define BQ_ 128
#define BK_ 64
#define QS_ 132
#define KS_ 68
#define ATTN_SMEM_FLOATS (64*QS_ + 64*KS_ + BK_*KS_ + BQ_*KS_)

// GEMM tiling
#define GSTRIDE 36                       // floats per smem row (32 data + 4 pad)
#define GEMM_TILE_FLOATS (128 * GSTRIDE) // one A or B tile
#define GEMM_SMEM_BYTES (4 * GEMM_TILE_FLOATS * 4)  // A0,B0,A1,B1 = 73728 B

// Scratch
__device__ float g_qkv[(size_t)NTOK_ * QKVN_];
__device__ float g_attn[(size_t)NTOK_ * INNER_];

// ---------------------------------------------------------------------------
__device__ __forceinline__ uint32_t f2tf32(float x) {
    uint32_t r;
    asm("cvt.rna.tf32.f32 %0, %1;" : "=r"(r) : "f"(x));
    return r;
}

#define MMA_TF32(c0, c1, c2, c3, a0, a1, a2, a3, b0, b1) \
    asm volatile("mma.sync.aligned.m16n8k8.row.col.f32.tf32.tf32.f32 " \
        "{%0,%1,%2,%3}, {%4,%5,%6,%7}, {%8,%9}, {%0,%1,%2,%3};" \
        : "+f"(c0), "+f"(c1), "+f"(c2), "+f"(c3) \
        : "r"(a0), "r"(a1), "r"(a2), "r"(a3), "r"(b0), "r"(b1))

// ---------------------------------------------------------------------------
// tf32 mma.sync GEMM: C[M,N] = A[M,512] * B[N,512]^T (+ bias)
// 128x128 CTA tile, 8 warps (64x32 each), K-chunk 32, double-buffered smem.
// Fragment k-mapping within a 32-chunk: frag(step s, col c*4+t) <-> k = 8t+2s+c
// => every thread's fragment data is a contiguous 8-float run (2x LDS.128).
// ---------------------------------------------------------------------------
__global__ __launch_bounds__(256) void gemm_mma(
    const float* __restrict__ A, const float* __restrict__ B,
    const float* __restrict__ bias, float* __restrict__ C, int N)
{
    extern __shared__ float smem[];
    float* Abuf[2] = { smem,                         smem + 2 * GEMM_TILE_FLOATS };
    float* Bbuf[2] = { smem + GEMM_TILE_FLOATS,      smem + 3 * GEMM_TILE_FLOATS };

    const int tid = threadIdx.x;
    const int wid = tid >> 5;
    const int lane = tid & 31;
    const int g = lane >> 2;       // group id (row within 8)
    const int t = lane & 3;        // thread-in-group
    const int bm = blockIdx.y * 128;
    const int bn = blockIdx.x * 128;
    const int mbase = (wid >> 2) * 64;   // warp m offset (0/64)
    const int nbase = (wid & 3) * 32;    // warp n offset (0/32/64/96)

    // GMEM load pattern: 8 threads per row, float4 each
    const int lrow = tid >> 3;          // 0..31
    const int lc4  = (tid & 7) << 2;    // 0,4..28

    float C0[4][4][4];                  // [mt][nt][frag]
#pragma unroll
    for (int mt = 0; mt < 4; mt++)
#pragma unroll
        for (int nt = 0; nt < 4; nt++)
#pragma unroll
            for (int f = 0; f < 4; f++) C0[mt][nt][f] = 0.0f;

    uint4 ldA[4], ldB[4];

    // ---- prologue: load chunk 0 ----
#pragma unroll
    for (int it = 0; it < 4; it++) {
        int row = lrow + it * 32;
        float4 va = *reinterpret_cast<const float4*>(&A[(size_t)(bm + row) * GK_ + lc4]);
        float4 vb = *reinterpret_cast<const float4*>(&B[(size_t)(bn + row) * GK_ + lc4]);
        ldA[it] = make_uint4(f2tf32(va.x), f2tf32(va.y), f2tf32(va.z), f2tf32(va.w));
        ldB[it] = make_uint4(f2tf32(vb.x), f2tf32(vb.y), f2tf32(vb.z), f2tf32(vb.w));
    }
#pragma unroll
    for (int it = 0; it < 4; it++) {
        int row = lrow + it * 32;
        *reinterpret_cast<uint4*>(&Abuf[0][row * GSTRIDE + lc4]) = ldA[it];
        *reinterpret_cast<uint4*>(&Bbuf[0][row * GSTRIDE + lc4]) = ldB[it];
    }
    __syncthreads();

    for (int kt = 0; kt < 16; kt++) {
        const int buf = kt & 1;

        if (kt < 15) {
            const int k0 = (kt + 1) * 32;
#pragma unroll
            for (int it = 0; it < 4; it++) {
                int row = lrow + it * 32;
                float4 va = *reinterpret_cast<const float4*>(&A[(size_t)(bm + row) * GK_ + k0 + lc4]);
                float4 vb = *reinterpret_cast<const float4*>(&B[(size_t)(bn + row) * GK_ + k0 + lc4]);
                ldA[it] = make_uint4(f2tf32(va.x), f2tf32(va.y), f2tf32(va.z), f2tf32(va.w));
                ldB[it] = make_uint4(f2tf32(vb.x), f2tf32(vb.y), f2tf32(vb.z), f2tf32(vb.w));
            }
        }

        // ---- compute on buf ----
        const uint32_t* As = reinterpret_cast<const uint32_t*>(Abuf[buf]);
        const uint32_t* Bs = reinterpret_cast<const uint32_t*>(Bbuf[buf]);
#pragma unroll
        for (int half = 0; half < 2; half++) {
            uint4 av[4][2];
            uint4 bv[4];
#pragma unroll
            for (int mt = 0; mt < 4; mt++) {
                int r0 = mbase + mt * 16 + g;
                av[mt][0] = *reinterpret_cast<const uint4*>(&As[r0 * GSTRIDE + 8 * t + 4 * half]);
                av[mt][1] = *reinterpret_cast<const uint4*>(&As[(r0 + 8) * GSTRIDE + 8 * t + 4 * half]);
            }
#pragma unroll
            for (int nt = 0; nt < 4; nt++) {
                int rn = nbase + nt * 8 + g;
                bv[nt] = *reinterpret_cast<const uint4*>(&Bs[rn * GSTRIDE + 8 * t + 4 * half]);
            }
#pragma unroll
            for (int ss = 0; ss < 2; ss++) {
#pragma unroll
                for (int mt = 0; mt < 4; mt++) {
                    uint32_t a0 = (ss == 0) ? av[mt][0].x : av[mt][0].z;
                    uint32_t a2 = (ss == 0) ? av[mt][0].y : av[mt][0].w;
                    uint32_t a1 = (ss == 0) ? av[mt][1].x : av[mt][1].z;
                    uint32_t a3 = (ss == 0) ? av[mt][1].y : av[mt][1].w;
#pragma unroll
                    for (int nt = 0; nt < 4; nt++) {
                        uint32_t b0 = (ss == 0) ? bv[nt].x : bv[nt].z;
                        uint32_t b1 = (ss == 0) ? bv[nt].y : bv[nt].w;
                        MMA_TF32(C0[mt][nt][0], C0[mt][nt][1], C0[mt][nt][2], C0[mt][nt][3],
                                 a0, a1, a2, a3, b0, b1);
                    }
                }
            }
        }

        if (kt < 15) {
            const int nbuf = (kt + 1) & 1;
#pragma unroll
            for (int it = 0; it < 4; it++) {
                int row = lrow + it * 32;
                *reinterpret_cast<uint4*>(&Abuf[nbuf][row * GSTRIDE + lc4]) = ldA[it];
                *reinterpret_cast<uint4*>(&Bbuf[nbuf][row * GSTRIDE + lc4]) = ldB[it];
            }
        }
        __syncthreads();
    }

    // ---- epilogue ----
#pragma unroll
    for (int mt = 0; mt < 4; mt++) {
        int row0 = bm + mbase + mt * 16 + g;
#pragma unroll
        for (int nt = 0; nt < 4; nt++) {
            int col = bn + nbase + nt * 8 + 2 * t;
            float bx = 0.f, by = 0.f;
            if (bias) { bx = bias[col]; by = bias[col + 1]; }
            float2 o0 = make_float2(C0[mt][nt][0] + bx, C0[mt][nt][1] + by);
            float2 o1 = make_float2(C0[mt][nt][2] + bx, C0[mt][nt][3] + by);
            *reinterpret_cast<float2*>(&C[(size_t)row0 * N + col]) = o0;
            *reinterpret_cast<float2*>(&C[(size_t)(row0 + 8) * N + col]) = o1;
        }
    }
}

// ---------------------------------------------------------------------------
// Axial RoPE in-place on q,k of g_qkv.
// ---------------------------------------------------------------------------
__global__ __launch_bounds__(256) void rope_kernel(float* __restrict__ qkv)
{
    int idx = blockIdx.x * blockDim.x + threadIdx.x;
    const int total = NTOK_ * NH_ * 32;
    if (idx >= total) return;

    int p   = idx & 31;
    int hh  = (idx >> 5) & 7;
    int tok = idx >> 8;
    int sp  = tok & (SEQ_ - 1);
    int i   = sp >> 5;
    int j   = sp & 31;

    float base = (1.0f + (float)(p & 15) * (127.0f / 15.0f)) * PI_F;
    float pos  = (p < 16) ? (-1.0f + (float)i * (2.0f / 31.0f))
                          : (-1.0f + (float)j * (2.0f / 31.0f));
    float th = pos * base;
    float s, c;
    sincosf(th, &s, &c);

    size_t col = (size_t)hh * HD_ + (size_t)p * 2;
    float* q = &qkv[(size_t)tok * QKVN_ + col];
    float* k = q + 512;

    float q0 = q[0], q1 = q[1];
    q[0] = q0 * c - q1 * s;
    q[1] = q1 * c + q0 * s;
    float k0 = k[0], k1 = k[1];
    k[0] = k0 * c - k1 * s;
    k[1] = k1 * c + k0 * s;
}

// ---------------------------------------------------------------------------
// Flash attention (fp32 SIMT, register online softmax) — unchanged (R3).
// ---------------------------------------------------------------------------
__global__ __launch_bounds__(256, 2) void attn_kernel(
    const float* __restrict__ qkv, float* __restrict__ outb)
{
    extern __shared__ float fsm[];
    float* sQ = fsm;
    float* sK = sQ + 64 * QS_;
    float* sV = sK + 64 * KS_;
    float* sP = sV + BK_ * KS_;

    const int bh = blockIdx.y;
    const int bt = bh >> 3;
    const int h  = bh & 7;
    const int q0 = blockIdx.x * BQ_;
    const int tid = threadIdx.x;
    const int tx = tid & 15;
    const int ty = tid >> 4;

    const size_t baseQ = ((size_t)bt * SEQ_ + q0) * QKVN_ + (size_t)h * HD_;
#pragma unroll
    for (int it = 0; it < 8; it++) {
        int idx = tid + it * 256;
        int row = idx >> 4;
        int d4  = (idx & 15) << 2;
        float4 v = *reinterpret_cast<const float4*>(&qkv[baseQ + (size_t)row * QKVN_ + d4]);
        sQ[(d4 + 0) * QS_ + row] = v.x;
        sQ[(d4 + 1) * QS_ + row] = v.y;
        sQ[(d4 + 2) * QS_ + row] = v.z;
        sQ[(d4 + 3) * QS_ + row] = v.w;
    }

    float O[8][4];
    float m[8], l[8];
#pragma unroll
    for (int i = 0; i < 8; i++) {
        m[i] = -1e30f; l[i] = 0.0f;
#pragma unroll
        for (int j = 0; j < 4; j++) O[i][j] = 0.0f;
    }

    for (int kt = 0; kt < SEQ_; kt += BK_) {
        const size_t baseK = ((size_t)bt * SEQ_ + kt) * QKVN_ + 512 + (size_t)h * HD_;
        const size_t baseV = baseK + 512;

        __syncthreads();
#pragma unroll
        for (int it = 0; it < 4; it++) {
            int idx = tid + it * 256;
            int row = idx >> 4;
            int d4  = (idx & 15) << 2;
            float4 kv = *reinterpret_cast<const float4*>(&qkv[baseK + (size_t)row * QKVN_ + d4]);
            sK[(d4 + 0) * KS_ + row] = kv.x;
            sK[(d4 + 1) * KS_ + row] = kv.y;
            sK[(d4 + 2) * KS_ + row] = kv.z;
            sK[(d4 + 3) * KS_ + row] = kv.w;
            float4 vv = *reinterpret_cast<const float4*>(&qkv[baseV + (size_t)row * QKVN_ + d4]);
            *reinterpret_cast<float4*>(&sV[row * KS_ + d4]) = vv;
        }
        __syncthreads();

        float s[8][4];
#pragma unroll
        for (int i = 0; i < 8; i++)
#pragma unroll
            for (int j = 0; j < 4; j++) s[i][j] = 0.0f;

#pragma unroll 4
        for (int d = 0; d < 64; d++) {
            float4 a0 = *reinterpret_cast<const float4*>(&sQ[d * QS_ + ty * 8]);
            float4 a1 = *reinterpret_cast<const float4*>(&sQ[d * QS_ + ty * 8 + 4]);
            float4 b  = *reinterpret_cast<const float4*>(&sK[d * KS_ + tx * 4]);
            float ra[8] = {a0.x, a0.y, a0.z, a0.w, a1.x, a1.y, a1.z, a1.w};
#pragma unroll
            for (int i = 0; i < 8; i++) {
                s[i][0] += ra[i] * b.x;
                s[i][1] += ra[i] * b.y;
                s[i][2] += ra[i] * b.z;
                s[i][3] += ra[i] * b.w;
            }
        }

#pragma unroll
        for (int i = 0; i < 8; i++) {
            float s0 = s[i][0] * 0.125f;
            float s1 = s[i][1] * 0.125f;
            float s2 = s[i][2] * 0.125f;
            float s3 = s[i][3] * 0.125f;
            float mx = fmaxf(fmaxf(s0, s1), fmaxf(s2, s3));
#pragma unroll
            for (int off = 8; off > 0; off >>= 1)
                mx = fmaxf(mx, __shfl_xor_sync(0xffffffffu, mx, off));
            float mnew  = fmaxf(m[i], mx);
            float alpha = __expf(m[i] - mnew);
            s0 = __expf(s0 - mnew);
            s1 = __expf(s1 - mnew);
            s2 = __expf(s2 - mnew);
            s3 = __expf(s3 - mnew);
            float sum = (s0 + s1) + (s2 + s3);
#pragma unroll
            for (int off = 8; off > 0; off >>= 1)
                sum += __shfl_xor_sync(0xffffffffu, sum, off);
            l[i] = l[i] * alpha + sum;
            m[i] = mnew;
            O[i][0] *= alpha; O[i][1] *= alpha; O[i][2] *= alpha; O[i][3] *= alpha;
            *reinterpret_cast<float4*>(&sP[(ty * 8 + i) * KS_ + tx * 4]) =
                make_float4(s0, s1, s2, s3);
        }
        __syncthreads();

#pragma unroll 4
        for (int c0 = 0; c0 < BK_; c0 += 4) {
            float4 v0 = *reinterpret_cast<const float4*>(&sV[(c0 + 0) * KS_ + tx * 4]);
            float4 v1 = *reinterpret_cast<const float4*>(&sV[(c0 + 1) * KS_ + tx * 4]);
            float4 v2 = *reinterpret_cast<const float4*>(&sV[(c0 + 2) * KS_ + tx * 4]);
            float4 v3 = *reinterpret_cast<const float4*>(&sV[(c0 + 3) * KS_ + tx * 4]);
#pragma unroll
            for (int i = 0; i < 8; i++) {
                float4 p = *reinterpret_cast<const float4*>(&sP[(ty * 8 + i) * KS_ + c0]);
                O[i][0] += p.x * v0.x + p.y * v1.x + p.z * v2.x + p.w * v3.x;
                O[i][1] += p.x * v0.y + p.y * v1.y + p.z * v2.y + p.w * v3.y;
                O[i][2] += p.x * v0.z + p.y * v1.z + p.z * v2.z + p.w * v3.z;
                O[i][3] += p.x * v0.w + p.y * v1.w + p.z * v2.w + p.w * v3.w;
            }
        }
    }

    const size_t outBase = ((size_t)bt * SEQ_ + q0) * INNER_ + (size_t)h * HD_;
#pragma unroll
    for (int i = 0; i < 8; i++) {
        float inv = 1.0f / l[i];
        float4 o = make_float4(O[i][0] * inv, O[i][1] * inv, O[i][2] * inv, O[i][3] * inv);
        *reinterpret_cast<float4*>(&outb[outBase + (size_t)(ty * 8 + i) * INNER_ + tx * 4]) = o;
    }
}

// ---------------------------------------------------------------------------
extern "C" void kernel_launch(void* const* d_in, const int* in_sizes, int n_in,
                              void* d_out, int out_size)
{
    const float* x     = (const float*)d_in[0];
    const float* w_qkv = (const float*)d_in[1];
    const float* w_out = (const float*)d_in[2];
    const float* b_out = (const float*)d_in[3];
    float* out = (float*)d_out;

    float* qkv = nullptr;
    float* attn = nullptr;
    cudaGetSymbolAddress((void**)&qkv, g_qkv);
    cudaGetSymbolAddress((void**)&attn, g_attn);

    static bool attr_set = false;
    if (!attr_set) {
        cudaFuncSetAttribute(gemm_mma,
                             cudaFuncAttributeMaxDynamicSharedMemorySize, GEMM_SMEM_BYTES);
        cudaFuncSetAttribute(attn_kernel,
                             cudaFuncAttributeMaxDynamicSharedMemorySize,
                             ATTN_SMEM_FLOATS * (int)sizeof(float));
        attr_set = true;
    }

    // 1) QKV projection (tf32 mma.sync)
    {
        dim3 grid(QKVN_ / 128, NTOK_ / 128);
        gemm_mma<<<grid, 256, GEMM_SMEM_BYTES>>>(x, w_qkv, nullptr, qkv, QKVN_);
    }

    // 2) RoPE
    {
        int total = NTOK_ * NH_ * 32;
        rope_kernel<<<(total + 255) / 256, 256>>>(qkv);
    }

    // 3) Attention
    {
        dim3 grid(SEQ_ / BQ_, BT_ * NH_);
        attn_kernel<<<grid, 256, ATTN_SMEM_FLOATS * sizeof(float)>>>(qkv, attn);
    }

    // 4) Output projection + bias (tf32 mma.sync)
    {
        dim3 grid(INNER_ / 128, NTOK_ / 128);
        gemm_mma<<<grid, 256, GEMM_SMEM_BYTES>>>(attn, w_out, b_out, out, INNER_);
    }
}

// round 6
// speedup vs baseline: 3.2867x; 1.7327x over previous
#include <cuda_runtime.h>
#include <math.h>
#include <stdint.h>

// Problem constants
#define BT_    16
#define NH_    8
#define HD_    64
#define SEQ_   1024
#define NTOK_  16384
#define DIM_   512
#define INNER_ 512
#define QKVN_  1536
#define GK_    512

#define PI_F 3.14159265358979323846f
#define LOG2E_F 1.4426950408889634f

// GEMM tiling
#define GSTRIDE 36
#define GEMM_TILE_FLOATS (128 * GSTRIDE)
#define GEMM_SMEM_BYTES (4 * GEMM_TILE_FLOATS * 4)

// Attention smem layout (uints/floats)
#define AQS_ 68                       // sQ/sK/sP stride
#define AVS_ 70                       // sVt stride
#define A_SQ_OFF   0
#define A_SK_OFF   (128 * AQS_)
#define A_SP_OFF   (A_SK_OFF + 64 * AQS_)
#define A_SVT_OFF  (A_SP_OFF + 128 * AQS_)
#define ATTN_SMEM_UINTS (A_SVT_OFF + 64 * AVS_)
#define ATTN_SMEM_BYTES (ATTN_SMEM_UINTS * 4)

// Scratch
__device__ float g_qkv[(size_t)NTOK_ * QKVN_];
__device__ float g_attn[(size_t)NTOK_ * INNER_];

// ---------------------------------------------------------------------------
__device__ __forceinline__ uint32_t f2tf32(float x) {
    uint32_t r;
    asm("cvt.rna.tf32.f32 %0, %1;" : "=r"(r) : "f"(x));
    return r;
}

#define MMA_TF32(c0, c1, c2, c3, a0, a1, a2, a3, b0, b1) \
    asm volatile("mma.sync.aligned.m16n8k8.row.col.f32.tf32.tf32.f32 " \
        "{%0,%1,%2,%3}, {%4,%5,%6,%7}, {%8,%9}, {%0,%1,%2,%3};" \
        : "+f"(c0), "+f"(c1), "+f"(c2), "+f"(c3) \
        : "r"(a0), "r"(a1), "r"(a2), "r"(a3), "r"(b0), "r"(b1))

// ---------------------------------------------------------------------------
// tf32 mma.sync GEMM: C[M,N] = A[M,512] * B[N,512]^T (+ bias)   (unchanged R5)
// ---------------------------------------------------------------------------
__global__ __launch_bounds__(256) void gemm_mma(
    const float* __restrict__ A, const float* __restrict__ B,
    const float* __restrict__ bias, float* __restrict__ C, int N)
{
    extern __shared__ float smem[];
    float* Abuf[2] = { smem,                    smem + 2 * GEMM_TILE_FLOATS };
    float* Bbuf[2] = { smem + GEMM_TILE_FLOATS, smem + 3 * GEMM_TILE_FLOATS };

    const int tid = threadIdx.x;
    const int wid = tid >> 5;
    const int lane = tid & 31;
    const int g = lane >> 2;
    const int t = lane & 3;
    const int bm = blockIdx.y * 128;
    const int bn = blockIdx.x * 128;
    const int mbase = (wid >> 2) * 64;
    const int nbase = (wid & 3) * 32;

    const int lrow = tid >> 3;
    const int lc4  = (tid & 7) << 2;

    float C0[4][4][4];
#pragma unroll
    for (int mt = 0; mt < 4; mt++)
#pragma unroll
        for (int nt = 0; nt < 4; nt++)
#pragma unroll
            for (int f = 0; f < 4; f++) C0[mt][nt][f] = 0.0f;

    uint4 ldA[4], ldB[4];

#pragma unroll
    for (int it = 0; it < 4; it++) {
        int row = lrow + it * 32;
        float4 va = *reinterpret_cast<const float4*>(&A[(size_t)(bm + row) * GK_ + lc4]);
        float4 vb = *reinterpret_cast<const float4*>(&B[(size_t)(bn + row) * GK_ + lc4]);
        ldA[it] = make_uint4(f2tf32(va.x), f2tf32(va.y), f2tf32(va.z), f2tf32(va.w));
        ldB[it] = make_uint4(f2tf32(vb.x), f2tf32(vb.y), f2tf32(vb.z), f2tf32(vb.w));
    }
#pragma unroll
    for (int it = 0; it < 4; it++) {
        int row = lrow + it * 32;
        *reinterpret_cast<uint4*>(&Abuf[0][row * GSTRIDE + lc4]) = ldA[it];
        *reinterpret_cast<uint4*>(&Bbuf[0][row * GSTRIDE + lc4]) = ldB[it];
    }
    __syncthreads();

    for (int kt = 0; kt < 16; kt++) {
        const int buf = kt & 1;

        if (kt < 15) {
            const int k0 = (kt + 1) * 32;
#pragma unroll
            for (int it = 0; it < 4; it++) {
                int row = lrow + it * 32;
                float4 va = *reinterpret_cast<const float4*>(&A[(size_t)(bm + row) * GK_ + k0 + lc4]);
                float4 vb = *reinterpret_cast<const float4*>(&B[(size_t)(bn + row) * GK_ + k0 + lc4]);
                ldA[it] = make_uint4(f2tf32(va.x), f2tf32(va.y), f2tf32(va.z), f2tf32(va.w));
                ldB[it] = make_uint4(f2tf32(vb.x), f2tf32(vb.y), f2tf32(vb.z), f2tf32(vb.w));
            }
        }

        const uint32_t* As = reinterpret_cast<const uint32_t*>(Abuf[buf]);
        const uint32_t* Bs = reinterpret_cast<const uint32_t*>(Bbuf[buf]);
#pragma unroll
        for (int half = 0; half < 2; half++) {
            uint4 av[4][2];
            uint4 bv[4];
#pragma unroll
            for (int mt = 0; mt < 4; mt++) {
                int r0 = mbase + mt * 16 + g;
                av[mt][0] = *reinterpret_cast<const uint4*>(&As[r0 * GSTRIDE + 8 * t + 4 * half]);
                av[mt][1] = *reinterpret_cast<const uint4*>(&As[(r0 + 8) * GSTRIDE + 8 * t + 4 * half]);
            }
#pragma unroll
            for (int nt = 0; nt < 4; nt++) {
                int rn = nbase + nt * 8 + g;
                bv[nt] = *reinterpret_cast<const uint4*>(&Bs[rn * GSTRIDE + 8 * t + 4 * half]);
            }
#pragma unroll
            for (int ss = 0; ss < 2; ss++) {
#pragma unroll
                for (int mt = 0; mt < 4; mt++) {
                    uint32_t a0 = (ss == 0) ? av[mt][0].x : av[mt][0].z;
                    uint32_t a2 = (ss == 0) ? av[mt][0].y : av[mt][0].w;
                    uint32_t a1 = (ss == 0) ? av[mt][1].x : av[mt][1].z;
                    uint32_t a3 = (ss == 0) ? av[mt][1].y : av[mt][1].w;
#pragma unroll
                    for (int nt = 0; nt < 4; nt++) {
                        uint32_t b0 = (ss == 0) ? bv[nt].x : bv[nt].z;
                        uint32_t b1 = (ss == 0) ? bv[nt].y : bv[nt].w;
                        MMA_TF32(C0[mt][nt][0], C0[mt][nt][1], C0[mt][nt][2], C0[mt][nt][3],
                                 a0, a1, a2, a3, b0, b1);
                    }
                }
            }
        }

        if (kt < 15) {
            const int nbuf = (kt + 1) & 1;
#pragma unroll
            for (int it = 0; it < 4; it++) {
                int row = lrow + it * 32;
                *reinterpret_cast<uint4*>(&Abuf[nbuf][row * GSTRIDE + lc4]) = ldA[it];
                *reinterpret_cast<uint4*>(&Bbuf[nbuf][row * GSTRIDE + lc4]) = ldB[it];
            }
        }
        __syncthreads();
    }

#pragma unroll
    for (int mt = 0; mt < 4; mt++) {
        int row0 = bm + mbase + mt * 16 + g;
#pragma unroll
        for (int nt = 0; nt < 4; nt++) {
            int col = bn + nbase + nt * 8 + 2 * t;
            float bx = 0.f, by = 0.f;
            if (bias) { bx = bias[col]; by = bias[col + 1]; }
            float2 o0 = make_float2(C0[mt][nt][0] + bx, C0[mt][nt][1] + by);
            float2 o1 = make_float2(C0[mt][nt][2] + bx, C0[mt][nt][3] + by);
            *reinterpret_cast<float2*>(&C[(size_t)row0 * N + col]) = o0;
            *reinterpret_cast<float2*>(&C[(size_t)(row0 + 8) * N + col]) = o1;
        }
    }
}

// ---------------------------------------------------------------------------
// Axial RoPE in-place on q,k of g_qkv.  (unchanged)
// ---------------------------------------------------------------------------
__global__ __launch_bounds__(256) void rope_kernel(float* __restrict__ qkv)
{
    int idx = blockIdx.x * blockDim.x + threadIdx.x;
    const int total = NTOK_ * NH_ * 32;
    if (idx >= total) return;

    int p   = idx & 31;
    int hh  = (idx >> 5) & 7;
    int tok = idx >> 8;
    int sp  = tok & (SEQ_ - 1);
    int i   = sp >> 5;
    int j   = sp & 31;

    float base = (1.0f + (float)(p & 15) * (127.0f / 15.0f)) * PI_F;
    float pos  = (p < 16) ? (-1.0f + (float)i * (2.0f / 31.0f))
                          : (-1.0f + (float)j * (2.0f / 31.0f));
    float th = pos * base;
    float s, c;
    sincosf(th, &s, &c);

    size_t col = (size_t)hh * HD_ + (size_t)p * 2;
    float* q = &qkv[(size_t)tok * QKVN_ + col];
    float* k = q + 512;

    float q0 = q[0], q1 = q[1];
    q[0] = q0 * c - q1 * s;
    q[1] = q1 * c + q0 * s;
    float k0 = k[0], k1 = k[1];
    k[0] = k0 * c - k1 * s;
    k[1] = k1 * c + k0 * s;
}

// ---------------------------------------------------------------------------
// Flash attention on tf32 mma.sync.
// Grid (8, 128). Block 128 (4 warps). Warp handles 32 q-rows; tile = 128q x 64k.
// S = Q K^T on HMMA (Q pre-scaled by 0.125*log2e), softmax in registers
// (exp2), P -> smem (warp-private, natural key cols), O += P V on HMMA
// with V transposed in smem (sVt[d][key], stride 70).
// ---------------------------------------------------------------------------
__global__ __launch_bounds__(128, 2) void attn_mma(
    const float* __restrict__ qkv, float* __restrict__ outb)
{
    extern __shared__ uint32_t asm_[];
    uint32_t* sQ  = asm_ + A_SQ_OFF;    // [128][68] tf32 (scaled)
    uint32_t* sK  = asm_ + A_SK_OFF;    // [64][68]  tf32
    uint32_t* sP  = asm_ + A_SP_OFF;    // [128][68] tf32
    uint32_t* sVt = asm_ + A_SVT_OFF;   // [64 d][70 key] tf32

    const int bh = blockIdx.y;
    const int bt = bh >> 3;
    const int h  = bh & 7;
    const int q0 = blockIdx.x * 128;
    const int tid = threadIdx.x;
    const int wid = tid >> 5;
    const int lane = tid & 31;
    const int g = lane >> 2;
    const int t = lane & 3;
    const int wq0 = wid * 32;

    const float qscale = 0.125f * LOG2E_F;

    // ---- Load Q tile (128 x 64) -> sQ as scaled tf32 ----
    const size_t baseQ = ((size_t)bt * SEQ_ + q0) * QKVN_ + (size_t)h * HD_;
    {
        const int row = tid >> 4;           // base row (advances by 8)
        const int c4  = (tid & 15) << 2;
#pragma unroll
        for (int it = 0; it < 16; it++) {
            int r = row + it * 8;
            float4 v = *reinterpret_cast<const float4*>(&qkv[baseQ + (size_t)r * QKVN_ + c4]);
            uint4 u = make_uint4(f2tf32(v.x * qscale), f2tf32(v.y * qscale),
                                 f2tf32(v.z * qscale), f2tf32(v.w * qscale));
            *reinterpret_cast<uint4*>(&sQ[r * AQS_ + c4]) = u;
        }
    }

    float O[2][8][4];
    float m_[2][2], l_[2][2];
#pragma unroll
    for (int mt = 0; mt < 2; mt++) {
#pragma unroll
        for (int r = 0; r < 2; r++) { m_[mt][r] = -1e30f; l_[mt][r] = 0.0f; }
#pragma unroll
        for (int nd = 0; nd < 8; nd++)
#pragma unroll
            for (int f = 0; f < 4; f++) O[mt][nd][f] = 0.0f;
    }

    for (int kt = 0; kt < 16; kt++) {
        const size_t baseK = ((size_t)bt * SEQ_ + kt * 64) * QKVN_ + 512 + (size_t)h * HD_;
        const size_t baseV = baseK + 512;

        __syncthreads();   // previous tile's sK/sVt consumers done (covers sQ on kt=0)
        {
            const int row = tid >> 4;
            const int c4  = (tid & 15) << 2;
#pragma unroll
            for (int it = 0; it < 8; it++) {
                int r = row + it * 8;       // 0..63
                float4 kv = *reinterpret_cast<const float4*>(&qkv[baseK + (size_t)r * QKVN_ + c4]);
                *reinterpret_cast<uint4*>(&sK[r * AQS_ + c4]) =
                    make_uint4(f2tf32(kv.x), f2tf32(kv.y), f2tf32(kv.z), f2tf32(kv.w));
                float4 vv = *reinterpret_cast<const float4*>(&qkv[baseV + (size_t)r * QKVN_ + c4]);
                sVt[(c4 + 0) * AVS_ + r] = f2tf32(vv.x);
                sVt[(c4 + 1) * AVS_ + r] = f2tf32(vv.y);
                sVt[(c4 + 2) * AVS_ + r] = f2tf32(vv.z);
                sVt[(c4 + 3) * AVS_ + r] = f2tf32(vv.w);
            }
        }
        __syncthreads();

        // ---- S = Q K^T (already in log2 units) ----
        float S[2][8][4];
#pragma unroll
        for (int mt = 0; mt < 2; mt++)
#pragma unroll
            for (int nt = 0; nt < 8; nt++)
#pragma unroll
                for (int f = 0; f < 4; f++) S[mt][nt][f] = 0.0f;

#pragma unroll
        for (int h2 = 0; h2 < 4; h2++) {
            const int koff = 32 * (h2 >> 1) + 4 * (h2 & 1) + 8 * t;
            uint4 av[2][2];
#pragma unroll
            for (int mt = 0; mt < 2; mt++) {
                int r0 = wq0 + 16 * mt + g;
                av[mt][0] = *reinterpret_cast<const uint4*>(&sQ[r0 * AQS_ + koff]);
                av[mt][1] = *reinterpret_cast<const uint4*>(&sQ[(r0 + 8) * AQS_ + koff]);
            }
            uint4 bv[8];
#pragma unroll
            for (int nt = 0; nt < 8; nt++)
                bv[nt] = *reinterpret_cast<const uint4*>(&sK[(8 * nt + g) * AQS_ + koff]);
#pragma unroll
            for (int ss = 0; ss < 2; ss++) {
#pragma unroll
                for (int mt = 0; mt < 2; mt++) {
                    uint32_t a0 = (ss == 0) ? av[mt][0].x : av[mt][0].z;
                    uint32_t a2 = (ss == 0) ? av[mt][0].y : av[mt][0].w;
                    uint32_t a1 = (ss == 0) ? av[mt][1].x : av[mt][1].z;
                    uint32_t a3 = (ss == 0) ? av[mt][1].y : av[mt][1].w;
#pragma unroll
                    for (int nt = 0; nt < 8; nt++) {
                        uint32_t b0 = (ss == 0) ? bv[nt].x : bv[nt].z;
                        uint32_t b1 = (ss == 0) ? bv[nt].y : bv[nt].w;
                        MMA_TF32(S[mt][nt][0], S[mt][nt][1], S[mt][nt][2], S[mt][nt][3],
                                 a0, a1, a2, a3, b0, b1);
                    }
                }
            }
        }

        // ---- Online softmax in registers (base-2) ----
#pragma unroll
        for (int mt = 0; mt < 2; mt++) {
#pragma unroll
            for (int r = 0; r < 2; r++) {
                float mx = -1e30f;
#pragma unroll
                for (int nt = 0; nt < 8; nt++)
                    mx = fmaxf(mx, fmaxf(S[mt][nt][2 * r], S[mt][nt][2 * r + 1]));
                mx = fmaxf(mx, __shfl_xor_sync(0xffffffffu, mx, 1));
                mx = fmaxf(mx, __shfl_xor_sync(0xffffffffu, mx, 2));
                float mo = m_[mt][r];
                float mn = fmaxf(mo, mx);
                float alpha = exp2f(mo - mn);
                float sum = 0.0f;
#pragma unroll
                for (int nt = 0; nt < 8; nt++) {
                    float p0 = exp2f(S[mt][nt][2 * r] - mn);
                    float p1 = exp2f(S[mt][nt][2 * r + 1] - mn);
                    S[mt][nt][2 * r] = p0;
                    S[mt][nt][2 * r + 1] = p1;
                    sum += p0 + p1;
                }
                sum += __shfl_xor_sync(0xffffffffu, sum, 1);
                sum += __shfl_xor_sync(0xffffffffu, sum, 2);
                m_[mt][r] = mn;
                l_[mt][r] = l_[mt][r] * alpha + sum;
#pragma unroll
                for (int nd = 0; nd < 8; nd++) {
                    O[mt][nd][2 * r]     *= alpha;
                    O[mt][nd][2 * r + 1] *= alpha;
                }
            }
        }

        // ---- Store P (tf32) to warp-private sP rows ----
#pragma unroll
        for (int mt = 0; mt < 2; mt++) {
            int r0 = wq0 + 16 * mt + g;
#pragma unroll
            for (int nt = 0; nt < 8; nt++) {
                uint2 lo = make_uint2(f2tf32(S[mt][nt][0]), f2tf32(S[mt][nt][1]));
                uint2 hi = make_uint2(f2tf32(S[mt][nt][2]), f2tf32(S[mt][nt][3]));
                *reinterpret_cast<uint2*>(&sP[r0 * AQS_ + 8 * nt + 2 * t]) = lo;
                *reinterpret_cast<uint2*>(&sP[(r0 + 8) * AQS_ + 8 * nt + 2 * t]) = hi;
            }
        }
        __syncwarp();

        // ---- O += P V  (A = P rows, B = Vt[d][key]) ----
#pragma unroll
        for (int h2 = 0; h2 < 4; h2++) {
            const int koff = 32 * (h2 >> 1) + 4 * (h2 & 1) + 8 * t;
            uint4 av[2][2];
#pragma unroll
            for (int mt = 0; mt < 2; mt++) {
                int r0 = wq0 + 16 * mt + g;
                av[mt][0] = *reinterpret_cast<const uint4*>(&sP[r0 * AQS_ + koff]);
                av[mt][1] = *reinterpret_cast<const uint4*>(&sP[(r0 + 8) * AQS_ + koff]);
            }
#pragma unroll
            for (int ss = 0; ss < 2; ss++) {
                uint2 bb[8];
#pragma unroll
                for (int nd = 0; nd < 8; nd++)
                    bb[nd] = *reinterpret_cast<const uint2*>(&sVt[(8 * nd + g) * AVS_ + koff + 2 * ss]);
#pragma unroll
                for (int mt = 0; mt < 2; mt++) {
                    uint32_t a0 = (ss == 0) ? av[mt][0].x : av[mt][0].z;
                    uint32_t a2 = (ss == 0) ? av[mt][0].y : av[mt][0].w;
                    uint32_t a1 = (ss == 0) ? av[mt][1].x : av[mt][1].z;
                    uint32_t a3 = (ss == 0) ? av[mt][1].y : av[mt][1].w;
#pragma unroll
                    for (int nd = 0; nd < 8; nd++) {
                        MMA_TF32(O[mt][nd][0], O[mt][nd][1], O[mt][nd][2], O[mt][nd][3],
                                 a0, a1, a2, a3, bb[nd].x, bb[nd].y);
                    }
                }
            }
        }
    }

    // ---- Normalize + write ----
    const size_t outBase = ((size_t)bt * SEQ_ + q0) * INNER_ + (size_t)h * HD_;
#pragma unroll
    for (int mt = 0; mt < 2; mt++) {
#pragma unroll
        for (int r = 0; r < 2; r++) {
            float inv = 1.0f / l_[mt][r];
            int row = wq0 + 16 * mt + g + 8 * r;
#pragma unroll
            for (int nd = 0; nd < 8; nd++) {
                float2 o = make_float2(O[mt][nd][2 * r] * inv, O[mt][nd][2 * r + 1] * inv);
                *reinterpret_cast<float2*>(&outb[outBase + (size_t)row * INNER_ + 8 * nd + 2 * t]) = o;
            }
        }
    }
}

// ---------------------------------------------------------------------------
extern "C" void kernel_launch(void* const* d_in, const int* in_sizes, int n_in,
                              void* d_out, int out_size)
{
    const float* x     = (const float*)d_in[0];
    const float* w_qkv = (const float*)d_in[1];
    const float* w_out = (const float*)d_in[2];
    const float* b_out = (const float*)d_in[3];
    float* out = (float*)d_out;

    float* qkv = nullptr;
    float* attn = nullptr;
    cudaGetSymbolAddress((void**)&qkv, g_qkv);
    cudaGetSymbolAddress((void**)&attn, g_attn);

    static bool attr_set = false;
    if (!attr_set) {
        cudaFuncSetAttribute(gemm_mma,
                             cudaFuncAttributeMaxDynamicSharedMemorySize, GEMM_SMEM_BYTES);
        cudaFuncSetAttribute(attn_mma,
                             cudaFuncAttributeMaxDynamicSharedMemorySize, ATTN_SMEM_BYTES);
        attr_set = true;
    }

    // 1) QKV projection (tf32 mma.sync)
    {
        dim3 grid(QKVN_ / 128, NTOK_ / 128);
        gemm_mma<<<grid, 256, GEMM_SMEM_BYTES>>>(x, w_qkv, nullptr, qkv, QKVN_);
    }

    // 2) RoPE
    {
        int total = NTOK_ * NH_ * 32;
        rope_kernel<<<(total + 255) / 256, 256>>>(qkv);
    }

    // 3) Attention (tf32 mma.sync flash)
    {
        dim3 grid(SEQ_ / 128, BT_ * NH_);
        attn_mma<<<grid, 128, ATTN_SMEM_BYTES>>>(qkv, attn);
    }

    // 4) Output projection + bias (tf32 mma.sync)
    {
        dim3 grid(INNER_ / 128, NTOK_ / 128);
        gemm_mma<<<grid, 256, GEMM_SMEM_BYTES>>>(attn, w_out, b_out, out, INNER_);
    }
}

// round 7
// speedup vs baseline: 3.7135x; 1.1298x over previous
#include <cuda_runtime.h>
#include <math.h>
#include <stdint.h>

// Problem constants
#define BT_    16
#define NH_    8
#define HD_    64
#define SEQ_   1024
#define NTOK_  16384
#define DIM_   512
#define INNER_ 512
#define QKVN_  1536
#define GK_    512

#define PI_F 3.14159265358979323846f
#define LOG2E_F 1.4426950408889634f

// GEMM tiling: 128x128 tile, K-chunk 32, 4-stage cp.async pipeline
#define GSTRIDE 36
#define STAGE_FLOATS (2 * 128 * GSTRIDE)           // A + B per stage = 9216
#define STAGE_BYTES  (STAGE_FLOATS * 4)            // 36864
#define GEMM_SMEM_BYTES (4 * STAGE_BYTES)          // 147456

// Attention smem layout
#define AQS_ 68
#define AVS_ 70
#define A_SQ_OFF   0
#define A_SK_OFF   (128 * AQS_)
#define A_SP_OFF   (A_SK_OFF + 64 * AQS_)
#define A_SVT_OFF  (A_SP_OFF + 128 * AQS_)
#define ATTN_SMEM_UINTS (A_SVT_OFF + 64 * AVS_)
#define ATTN_SMEM_BYTES (ATTN_SMEM_UINTS * 4)

// Scratch
__device__ float g_qkv[(size_t)NTOK_ * QKVN_];
__device__ float g_attn[(size_t)NTOK_ * INNER_];
__device__ float g_x[(size_t)NTOK_ * DIM_];      // tf32-rounded x
__device__ float g_wq[(size_t)QKVN_ * DIM_];     // tf32-rounded w_qkv
__device__ float g_wo[(size_t)INNER_ * DIM_];    // tf32-rounded w_out

// ---------------------------------------------------------------------------
__device__ __forceinline__ uint32_t f2tf32(float x) {
    uint32_t r;
    asm("cvt.rna.tf32.f32 %0, %1;" : "=r"(r) : "f"(x));
    return r;
}
__device__ __forceinline__ uint32_t smem_u32(const void* p) {
    uint32_t a;
    asm("{ .reg .u64 t; cvta.to.shared.u64 t, %1; cvt.u32.u64 %0, t; }"
        : "=r"(a) : "l"(p));
    return a;
}
__device__ __forceinline__ void cp16(uint32_t saddr, const void* gaddr) {
    asm volatile("cp.async.cg.shared.global [%0], [%1], 16;"
                 :: "r"(saddr), "l"(gaddr) : "memory");
}
#define CP_COMMIT() asm volatile("cp.async.commit_group;" ::: "memory")
#define CP_WAIT2()  asm volatile("cp.async.wait_group 2;" ::: "memory")

#define MMA_TF32(c0, c1, c2, c3, a0, a1, a2, a3, b0, b1) \
    asm volatile("mma.sync.aligned.m16n8k8.row.col.f32.tf32.tf32.f32 " \
        "{%0,%1,%2,%3}, {%4,%5,%6,%7}, {%8,%9}, {%0,%1,%2,%3};" \
        : "+f"(c0), "+f"(c1), "+f"(c2), "+f"(c3) \
        : "r"(a0), "r"(a1), "r"(a2), "r"(a3), "r"(b0), "r"(b1))

// ---------------------------------------------------------------------------
// Round fp32 -> tf32-in-fp32 (RNA), vectorized.
// ---------------------------------------------------------------------------
__global__ __launch_bounds__(256) void round_tf32(
    const float* __restrict__ src, float* __restrict__ dst, int n4)
{
    int i = blockIdx.x * blockDim.x + threadIdx.x;
    if (i >= n4) return;
    float4 v = reinterpret_cast<const float4*>(src)[i];
    uint4 u = make_uint4(f2tf32(v.x), f2tf32(v.y), f2tf32(v.z), f2tf32(v.w));
    reinterpret_cast<uint4*>(dst)[i] = u;
}

// ---------------------------------------------------------------------------
// tf32 mma.sync GEMM with 4-stage cp.async pipeline.
// C[M,N] = A[M,512] * B[N,512]^T (+ bias). A,B pre-rounded to tf32.
// ---------------------------------------------------------------------------
__global__ __launch_bounds__(256) void gemm_mma(
    const float* __restrict__ A, const float* __restrict__ B,
    const float* __restrict__ bias, float* __restrict__ C, int N)
{
    extern __shared__ float smem[];
    const uint32_t sbase = smem_u32(smem);

    const int tid = threadIdx.x;
    const int wid = tid >> 5;
    const int lane = tid & 31;
    const int g = lane >> 2;
    const int t = lane & 3;
    const int bm = blockIdx.y * 128;
    const int bn = blockIdx.x * 128;
    const int mbase = (wid >> 2) * 64;
    const int nbase = (wid & 3) * 32;

    auto issue = [&](int stage, int k0) {
        uint32_t sA = sbase + (uint32_t)stage * STAGE_BYTES;
        uint32_t sB = sA + 128 * GSTRIDE * 4;
#pragma unroll
        for (int it = 0; it < 4; it++) {
            int idx = tid + it * 256;          // 0..1023
            int row = idx >> 3;                // 0..127
            int seg = (idx & 7) << 2;          // 0,4..28 floats
            uint32_t so = (uint32_t)(row * (GSTRIDE * 4) + seg * 4);
            cp16(sA + so, &A[(size_t)(bm + row) * GK_ + k0 + seg]);
            cp16(sB + so, &B[(size_t)(bn + row) * GK_ + k0 + seg]);
        }
    };

    float C0[4][4][4];
#pragma unroll
    for (int mt = 0; mt < 4; mt++)
#pragma unroll
        for (int nt = 0; nt < 4; nt++)
#pragma unroll
            for (int f = 0; f < 4; f++) C0[mt][nt][f] = 0.0f;

    // Prologue: stages 0..2
#pragma unroll
    for (int s = 0; s < 3; s++) {
        issue(s, s * 32);
        CP_COMMIT();
    }

    for (int kt = 0; kt < 16; kt++) {
        CP_WAIT2();
        __syncthreads();

        // Issue chunk kt+3 (or empty commit to keep group count constant)
        if (kt + 3 < 16) issue((kt + 3) & 3, (kt + 3) * 32);
        CP_COMMIT();

        const int buf = kt & 3;
        const uint32_t* As = reinterpret_cast<const uint32_t*>(smem) + buf * STAGE_FLOATS;
        const uint32_t* Bs = As + 128 * GSTRIDE;

#pragma unroll
        for (int half = 0; half < 2; half++) {
            uint4 av[4][2];
            uint4 bv[4];
#pragma unroll
            for (int mt = 0; mt < 4; mt++) {
                int r0 = mbase + mt * 16 + g;
                av[mt][0] = *reinterpret_cast<const uint4*>(&As[r0 * GSTRIDE + 8 * t + 4 * half]);
                av[mt][1] = *reinterpret_cast<const uint4*>(&As[(r0 + 8) * GSTRIDE + 8 * t + 4 * half]);
            }
#pragma unroll
            for (int nt = 0; nt < 4; nt++) {
                int rn = nbase + nt * 8 + g;
                bv[nt] = *reinterpret_cast<const uint4*>(&Bs[rn * GSTRIDE + 8 * t + 4 * half]);
            }
#pragma unroll
            for (int ss = 0; ss < 2; ss++) {
#pragma unroll
                for (int mt = 0; mt < 4; mt++) {
                    uint32_t a0 = (ss == 0) ? av[mt][0].x : av[mt][0].z;
                    uint32_t a2 = (ss == 0) ? av[mt][0].y : av[mt][0].w;
                    uint32_t a1 = (ss == 0) ? av[mt][1].x : av[mt][1].z;
                    uint32_t a3 = (ss == 0) ? av[mt][1].y : av[mt][1].w;
#pragma unroll
                    for (int nt = 0; nt < 4; nt++) {
                        uint32_t b0 = (ss == 0) ? bv[nt].x : bv[nt].z;
                        uint32_t b1 = (ss == 0) ? bv[nt].y : bv[nt].w;
                        MMA_TF32(C0[mt][nt][0], C0[mt][nt][1], C0[mt][nt][2], C0[mt][nt][3],
                                 a0, a1, a2, a3, b0, b1);
                    }
                }
            }
        }
        __syncthreads();
    }

#pragma unroll
    for (int mt = 0; mt < 4; mt++) {
        int row0 = bm + mbase + mt * 16 + g;
#pragma unroll
        for (int nt = 0; nt < 4; nt++) {
            int col = bn + nbase + nt * 8 + 2 * t;
            float bx = 0.f, by = 0.f;
            if (bias) { bx = bias[col]; by = bias[col + 1]; }
            float2 o0 = make_float2(C0[mt][nt][0] + bx, C0[mt][nt][1] + by);
            float2 o1 = make_float2(C0[mt][nt][2] + bx, C0[mt][nt][3] + by);
            *reinterpret_cast<float2*>(&C[(size_t)row0 * N + col]) = o0;
            *reinterpret_cast<float2*>(&C[(size_t)(row0 + 8) * N + col]) = o1;
        }
    }
}

// ---------------------------------------------------------------------------
// Axial RoPE in-place on q,k of g_qkv. (unchanged)
// ---------------------------------------------------------------------------
__global__ __launch_bounds__(256) void rope_kernel(float* __restrict__ qkv)
{
    int idx = blockIdx.x * blockDim.x + threadIdx.x;
    const int total = NTOK_ * NH_ * 32;
    if (idx >= total) return;

    int p   = idx & 31;
    int hh  = (idx >> 5) & 7;
    int tok = idx >> 8;
    int sp  = tok & (SEQ_ - 1);
    int i   = sp >> 5;
    int j   = sp & 31;

    float base = (1.0f + (float)(p & 15) * (127.0f / 15.0f)) * PI_F;
    float pos  = (p < 16) ? (-1.0f + (float)i * (2.0f / 31.0f))
                          : (-1.0f + (float)j * (2.0f / 31.0f));
    float th = pos * base;
    float s, c;
    sincosf(th, &s, &c);

    size_t col = (size_t)hh * HD_ + (size_t)p * 2;
    float* q = &qkv[(size_t)tok * QKVN_ + col];
    float* k = q + 512;

    float q0 = q[0], q1 = q[1];
    q[0] = q0 * c - q1 * s;
    q[1] = q1 * c + q0 * s;
    float k0 = k[0], k1 = k[1];
    k[0] = k0 * c - k1 * s;
    k[1] = k1 * c + k0 * s;
}

// ---------------------------------------------------------------------------
// Flash attention on tf32 mma.sync (R6), epilogue now stores tf32-rounded
// output so the out-projection can cp.async raw data.
// ---------------------------------------------------------------------------
__global__ __launch_bounds__(128, 2) void attn_mma(
    const float* __restrict__ qkv, float* __restrict__ outb)
{
    extern __shared__ uint32_t asm_[];
    uint32_t* sQ  = asm_ + A_SQ_OFF;
    uint32_t* sK  = asm_ + A_SK_OFF;
    uint32_t* sP  = asm_ + A_SP_OFF;
    uint32_t* sVt = asm_ + A_SVT_OFF;

    const int bh = blockIdx.y;
    const int bt = bh >> 3;
    const int h  = bh & 7;
    const int q0 = blockIdx.x * 128;
    const int tid = threadIdx.x;
    const int wid = tid >> 5;
    const int lane = tid & 31;
    const int g = lane >> 2;
    const int t = lane & 3;
    const int wq0 = wid * 32;

    const float qscale = 0.125f * LOG2E_F;

    const size_t baseQ = ((size_t)bt * SEQ_ + q0) * QKVN_ + (size_t)h * HD_;
    {
        const int row = tid >> 4;
        const int c4  = (tid & 15) << 2;
#pragma unroll
        for (int it = 0; it < 16; it++) {
            int r = row + it * 8;
            float4 v = *reinterpret_cast<const float4*>(&qkv[baseQ + (size_t)r * QKVN_ + c4]);
            uint4 u = make_uint4(f2tf32(v.x * qscale), f2tf32(v.y * qscale),
                                 f2tf32(v.z * qscale), f2tf32(v.w * qscale));
            *reinterpret_cast<uint4*>(&sQ[r * AQS_ + c4]) = u;
        }
    }

    float O[2][8][4];
    float m_[2][2], l_[2][2];
#pragma unroll
    for (int mt = 0; mt < 2; mt++) {
#pragma unroll
        for (int r = 0; r < 2; r++) { m_[mt][r] = -1e30f; l_[mt][r] = 0.0f; }
#pragma unroll
        for (int nd = 0; nd < 8; nd++)
#pragma unroll
            for (int f = 0; f < 4; f++) O[mt][nd][f] = 0.0f;
    }

    for (int kt = 0; kt < 16; kt++) {
        const size_t baseK = ((size_t)bt * SEQ_ + kt * 64) * QKVN_ + 512 + (size_t)h * HD_;
        const size_t baseV = baseK + 512;

        __syncthreads();
        {
            const int row = tid >> 4;
            const int c4  = (tid & 15) << 2;
#pragma unroll
            for (int it = 0; it < 8; it++) {
                int r = row + it * 8;
                float4 kv = *reinterpret_cast<const float4*>(&qkv[baseK + (size_t)r * QKVN_ + c4]);
                *reinterpret_cast<uint4*>(&sK[r * AQS_ + c4]) =
                    make_uint4(f2tf32(kv.x), f2tf32(kv.y), f2tf32(kv.z), f2tf32(kv.w));
                float4 vv = *reinterpret_cast<const float4*>(&qkv[baseV + (size_t)r * QKVN_ + c4]);
                sVt[(c4 + 0) * AVS_ + r] = f2tf32(vv.x);
                sVt[(c4 + 1) * AVS_ + r] = f2tf32(vv.y);
                sVt[(c4 + 2) * AVS_ + r] = f2tf32(vv.z);
                sVt[(c4 + 3) * AVS_ + r] = f2tf32(vv.w);
            }
        }
        __syncthreads();

        float S[2][8][4];
#pragma unroll
        for (int mt = 0; mt < 2; mt++)
#pragma unroll
            for (int nt = 0; nt < 8; nt++)
#pragma unroll
                for (int f = 0; f < 4; f++) S[mt][nt][f] = 0.0f;

#pragma unroll
        for (int h2 = 0; h2 < 4; h2++) {
            const int koff = 32 * (h2 >> 1) + 4 * (h2 & 1) + 8 * t;
            uint4 av[2][2];
#pragma unroll
            for (int mt = 0; mt < 2; mt++) {
                int r0 = wq0 + 16 * mt + g;
                av[mt][0] = *reinterpret_cast<const uint4*>(&sQ[r0 * AQS_ + koff]);
                av[mt][1] = *reinterpret_cast<const uint4*>(&sQ[(r0 + 8) * AQS_ + koff]);
            }
            uint4 bv[8];
#pragma unroll
            for (int nt = 0; nt < 8; nt++)
                bv[nt] = *reinterpret_cast<const uint4*>(&sK[(8 * nt + g) * AQS_ + koff]);
#pragma unroll
            for (int ss = 0; ss < 2; ss++) {
#pragma unroll
                for (int mt = 0; mt < 2; mt++) {
                    uint32_t a0 = (ss == 0) ? av[mt][0].x : av[mt][0].z;
                    uint32_t a2 = (ss == 0) ? av[mt][0].y : av[mt][0].w;
                    uint32_t a1 = (ss == 0) ? av[mt][1].x : av[mt][1].z;
                    uint32_t a3 = (ss == 0) ? av[mt][1].y : av[mt][1].w;
#pragma unroll
                    for (int nt = 0; nt < 8; nt++) {
                        uint32_t b0 = (ss == 0) ? bv[nt].x : bv[nt].z;
                        uint32_t b1 = (ss == 0) ? bv[nt].y : bv[nt].w;
                        MMA_TF32(S[mt][nt][0], S[mt][nt][1], S[mt][nt][2], S[mt][nt][3],
                                 a0, a1, a2, a3, b0, b1);
                    }
                }
            }
        }

#pragma unroll
        for (int mt = 0; mt < 2; mt++) {
#pragma unroll
            for (int r = 0; r < 2; r++) {
                float mx = -1e30f;
#pragma unroll
                for (int nt = 0; nt < 8; nt++)
                    mx = fmaxf(mx, fmaxf(S[mt][nt][2 * r], S[mt][nt][2 * r + 1]));
                mx = fmaxf(mx, __shfl_xor_sync(0xffffffffu, mx, 1));
                mx = fmaxf(mx, __shfl_xor_sync(0xffffffffu, mx, 2));
                float mo = m_[mt][r];
                float mn = fmaxf(mo, mx);
                float alpha = exp2f(mo - mn);
                float sum = 0.0f;
#pragma unroll
                for (int nt = 0; nt < 8; nt++) {
                    float p0 = exp2f(S[mt][nt][2 * r] - mn);
                    float p1 = exp2f(S[mt][nt][2 * r + 1] - mn);
                    S[mt][nt][2 * r] = p0;
                    S[mt][nt][2 * r + 1] = p1;
                    sum += p0 + p1;
                }
                sum += __shfl_xor_sync(0xffffffffu, sum, 1);
                sum += __shfl_xor_sync(0xffffffffu, sum, 2);
                m_[mt][r] = mn;
                l_[mt][r] = l_[mt][r] * alpha + sum;
#pragma unroll
                for (int nd = 0; nd < 8; nd++) {
                    O[mt][nd][2 * r]     *= alpha;
                    O[mt][nd][2 * r + 1] *= alpha;
                }
            }
        }

#pragma unroll
        for (int mt = 0; mt < 2; mt++) {
            int r0 = wq0 + 16 * mt + g;
#pragma unroll
            for (int nt = 0; nt < 8; nt++) {
                uint2 lo = make_uint2(f2tf32(S[mt][nt][0]), f2tf32(S[mt][nt][1]));
                uint2 hi = make_uint2(f2tf32(S[mt][nt][2]), f2tf32(S[mt][nt][3]));
                *reinterpret_cast<uint2*>(&sP[r0 * AQS_ + 8 * nt + 2 * t]) = lo;
                *reinterpret_cast<uint2*>(&sP[(r0 + 8) * AQS_ + 8 * nt + 2 * t]) = hi;
            }
        }
        __syncwarp();

#pragma unroll
        for (int h2 = 0; h2 < 4; h2++) {
            const int koff = 32 * (h2 >> 1) + 4 * (h2 & 1) + 8 * t;
            uint4 av[2][2];
#pragma unroll
            for (int mt = 0; mt < 2; mt++) {
                int r0 = wq0 + 16 * mt + g;
                av[mt][0] = *reinterpret_cast<const uint4*>(&sP[r0 * AQS_ + koff]);
                av[mt][1] = *reinterpret_cast<const uint4*>(&sP[(r0 + 8) * AQS_ + koff]);
            }
#pragma unroll
            for (int ss = 0; ss < 2; ss++) {
                uint2 bb[8];
#pragma unroll
                for (int nd = 0; nd < 8; nd++)
                    bb[nd] = *reinterpret_cast<const uint2*>(&sVt[(8 * nd + g) * AVS_ + koff + 2 * ss]);
#pragma unroll
                for (int mt = 0; mt < 2; mt++) {
                    uint32_t a0 = (ss == 0) ? av[mt][0].x : av[mt][0].z;
                    uint32_t a2 = (ss == 0) ? av[mt][0].y : av[mt][0].w;
                    uint32_t a1 = (ss == 0) ? av[mt][1].x : av[mt][1].z;
                    uint32_t a3 = (ss == 0) ? av[mt][1].y : av[mt][1].w;
#pragma unroll
                    for (int nd = 0; nd < 8; nd++) {
                        MMA_TF32(O[mt][nd][0], O[mt][nd][1], O[mt][nd][2], O[mt][nd][3],
                                 a0, a1, a2, a3, bb[nd].x, bb[nd].y);
                    }
                }
            }
        }
    }

    // ---- Normalize + write tf32-rounded (for cp.async out-proj) ----
    const size_t outBase = ((size_t)bt * SEQ_ + q0) * INNER_ + (size_t)h * HD_;
#pragma unroll
    for (int mt = 0; mt < 2; mt++) {
#pragma unroll
        for (int r = 0; r < 2; r++) {
            float inv = 1.0f / l_[mt][r];
            int row = wq0 + 16 * mt + g + 8 * r;
#pragma unroll
            for (int nd = 0; nd < 8; nd++) {
                uint2 o = make_uint2(f2tf32(O[mt][nd][2 * r] * inv),
                                     f2tf32(O[mt][nd][2 * r + 1] * inv));
                *reinterpret_cast<uint2*>(&outb[outBase + (size_t)row * INNER_ + 8 * nd + 2 * t]) = o;
            }
        }
    }
}

// ---------------------------------------------------------------------------
extern "C" void kernel_launch(void* const* d_in, const int* in_sizes, int n_in,
                              void* d_out, int out_size)
{
    const float* x     = (const float*)d_in[0];
    const float* w_qkv = (const float*)d_in[1];
    const float* w_out = (const float*)d_in[2];
    const float* b_out = (const float*)d_in[3];
    float* out = (float*)d_out;

    float* qkv = nullptr; float* attn = nullptr;
    float* xr = nullptr;  float* wq = nullptr;  float* wo = nullptr;
    cudaGetSymbolAddress((void**)&qkv, g_qkv);
    cudaGetSymbolAddress((void**)&attn, g_attn);
    cudaGetSymbolAddress((void**)&xr, g_x);
    cudaGetSymbolAddress((void**)&wq, g_wq);
    cudaGetSymbolAddress((void**)&wo, g_wo);

    static bool attr_set = false;
    if (!attr_set) {
        cudaFuncSetAttribute(gemm_mma,
                             cudaFuncAttributeMaxDynamicSharedMemorySize, GEMM_SMEM_BYTES);
        cudaFuncSetAttribute(attn_mma,
                             cudaFuncAttributeMaxDynamicSharedMemorySize, ATTN_SMEM_BYTES);
        attr_set = true;
    }

    // 0) Round inputs to tf32-in-fp32
    {
        int n4x = NTOK_ * DIM_ / 4;
        round_tf32<<<(n4x + 255) / 256, 256>>>(x, xr, n4x);
        int n4q = QKVN_ * DIM_ / 4;
        round_tf32<<<(n4q + 255) / 256, 256>>>(w_qkv, wq, n4q);
        int n4o = INNER_ * DIM_ / 4;
        round_tf32<<<(n4o + 255) / 256, 256>>>(w_out, wo, n4o);
    }

    // 1) QKV projection
    {
        dim3 grid(QKVN_ / 128, NTOK_ / 128);
        gemm_mma<<<grid, 256, GEMM_SMEM_BYTES>>>(xr, wq, nullptr, qkv, QKVN_);
    }

    // 2) RoPE
    {
        int total = NTOK_ * NH_ * 32;
        rope_kernel<<<(total + 255) / 256, 256>>>(qkv);
    }

    // 3) Attention
    {
        dim3 grid(SEQ_ / 128, BT_ * NH_);
        attn_mma<<<grid, 128, ATTN_SMEM_BYTES>>>(qkv, attn);
    }

    // 4) Output projection + bias
    {
        dim3 grid(INNER_ / 128, NTOK_ / 128);
        gemm_mma<<<grid, 256, GEMM_SMEM_BYTES>>>(attn, wo, b_out, out, INNER_);
    }
}

// round 8
// speedup vs baseline: 4.0327x; 1.0860x over previous
#include <cuda_runtime.h>
#include <math.h>
#include <stdint.h>

// Problem constants
#define BT_    16
#define NH_    8
#define HD_    64
#define SEQ_   1024
#define NTOK_  16384
#define DIM_   512
#define INNER_ 512
#define QKVN_  1536
#define GK_    512

#define PI_F 3.14159265358979323846f
#define LOG2E_F 1.4426950408889634f

// GEMM tiling: 128x128 tile, K-chunk 32, 3-stage cp.async pipeline, 2 CTA/SM
#define GSTRIDE 36
#define STAGE_FLOATS (2 * 128 * GSTRIDE)           // A + B per stage = 9216
#define STAGE_BYTES  (STAGE_FLOATS * 4)            // 36864
#define GSTAGES 3
#define GEMM_SMEM_BYTES (GSTAGES * STAGE_BYTES)    // 110592

// Attention smem layout
#define AQS_ 68
#define AVS_ 70
#define A_SQ_OFF   0
#define A_SK_OFF   (128 * AQS_)
#define A_SP_OFF   (A_SK_OFF + 64 * AQS_)
#define A_SVT_OFF  (A_SP_OFF + 128 * AQS_)
#define ATTN_SMEM_UINTS (A_SVT_OFF + 64 * AVS_)
#define ATTN_SMEM_BYTES (ATTN_SMEM_UINTS * 4)

// Scratch
__device__ float g_qkv[(size_t)NTOK_ * QKVN_];
__device__ float g_attn[(size_t)NTOK_ * INNER_];
__device__ float g_x[(size_t)NTOK_ * DIM_];      // tf32-rounded x
__device__ float g_wq[(size_t)QKVN_ * DIM_];     // tf32-rounded w_qkv
__device__ float g_wo[(size_t)INNER_ * DIM_];    // tf32-rounded w_out

// ---------------------------------------------------------------------------
__device__ __forceinline__ uint32_t f2tf32(float x) {
    uint32_t r;
    asm("cvt.rna.tf32.f32 %0, %1;" : "=r"(r) : "f"(x));
    return r;
}
__device__ __forceinline__ uint32_t smem_u32(const void* p) {
    uint32_t a;
    asm("{ .reg .u64 t; cvta.to.shared.u64 t, %1; cvt.u32.u64 %0, t; }"
        : "=r"(a) : "l"(p));
    return a;
}
__device__ __forceinline__ void cp16(uint32_t saddr, const void* gaddr) {
    asm volatile("cp.async.cg.shared.global [%0], [%1], 16;"
                 :: "r"(saddr), "l"(gaddr) : "memory");
}
#define CP_COMMIT() asm volatile("cp.async.commit_group;" ::: "memory")
#define CP_WAIT1()  asm volatile("cp.async.wait_group 1;" ::: "memory")

#define MMA_TF32(c0, c1, c2, c3, a0, a1, a2, a3, b0, b1) \
    asm volatile("mma.sync.aligned.m16n8k8.row.col.f32.tf32.tf32.f32 " \
        "{%0,%1,%2,%3}, {%4,%5,%6,%7}, {%8,%9}, {%0,%1,%2,%3};" \
        : "+f"(c0), "+f"(c1), "+f"(c2), "+f"(c3) \
        : "r"(a0), "r"(a1), "r"(a2), "r"(a3), "r"(b0), "r"(b1))

// ---------------------------------------------------------------------------
// Round fp32 -> tf32-in-fp32 (RNA), vectorized.
// ---------------------------------------------------------------------------
__global__ __launch_bounds__(256) void round_tf32(
    const float* __restrict__ src, float* __restrict__ dst, int n4)
{
    int i = blockIdx.x * blockDim.x + threadIdx.x;
    if (i >= n4) return;
    float4 v = reinterpret_cast<const float4*>(src)[i];
    uint4 u = make_uint4(f2tf32(v.x), f2tf32(v.y), f2tf32(v.z), f2tf32(v.w));
    reinterpret_cast<uint4*>(dst)[i] = u;
}

// ---------------------------------------------------------------------------
// tf32 mma.sync GEMM, 3-stage cp.async pipeline, 2 CTAs/SM.
// C[M,N] = A[M,512] * B[N,512]^T (+ bias). A,B pre-rounded to tf32.
// ---------------------------------------------------------------------------
__global__ __launch_bounds__(256, 2) void gemm_mma(
    const float* __restrict__ A, const float* __restrict__ B,
    const float* __restrict__ bias, float* __restrict__ C, int N)
{
    extern __shared__ float smem[];
    const uint32_t sbase = smem_u32(smem);

    const int tid = threadIdx.x;
    const int wid = tid >> 5;
    const int lane = tid & 31;
    const int g = lane >> 2;
    const int t = lane & 3;
    const int bm = blockIdx.y * 128;
    const int bn = blockIdx.x * 128;
    const int mbase = (wid >> 2) * 64;
    const int nbase = (wid & 3) * 32;

    auto issue = [&](int stage, int k0) {
        uint32_t sA = sbase + (uint32_t)stage * STAGE_BYTES;
        uint32_t sB = sA + 128 * GSTRIDE * 4;
#pragma unroll
        for (int it = 0; it < 4; it++) {
            int idx = tid + it * 256;          // 0..1023
            int row = idx >> 3;                // 0..127
            int seg = (idx & 7) << 2;          // 0,4..28 floats
            uint32_t so = (uint32_t)(row * (GSTRIDE * 4) + seg * 4);
            cp16(sA + so, &A[(size_t)(bm + row) * GK_ + k0 + seg]);
            cp16(sB + so, &B[(size_t)(bn + row) * GK_ + k0 + seg]);
        }
    };

    float C0[4][4][4];
#pragma unroll
    for (int mt = 0; mt < 4; mt++)
#pragma unroll
        for (int nt = 0; nt < 4; nt++)
#pragma unroll
            for (int f = 0; f < 4; f++) C0[mt][nt][f] = 0.0f;

    // Prologue: stages 0,1
    issue(0, 0);  CP_COMMIT();
    issue(1, 32); CP_COMMIT();

    for (int kt = 0; kt < 16; kt++) {
        CP_WAIT1();
        __syncthreads();

        // Issue chunk kt+2 into stage (kt+2)%3 (free since iter kt-1's barrier)
        if (kt + 2 < 16) issue((kt + 2) % GSTAGES, (kt + 2) * 32);
        CP_COMMIT();   // always commit (possibly empty) to keep group count exact

        const int buf = kt % GSTAGES;
        const uint32_t* As = reinterpret_cast<const uint32_t*>(smem) + buf * STAGE_FLOATS;
        const uint32_t* Bs = As + 128 * GSTRIDE;

#pragma unroll
        for (int half = 0; half < 2; half++) {
            uint4 av[4][2];
            uint4 bv[4];
#pragma unroll
            for (int mt = 0; mt < 4; mt++) {
                int r0 = mbase + mt * 16 + g;
                av[mt][0] = *reinterpret_cast<const uint4*>(&As[r0 * GSTRIDE + 8 * t + 4 * half]);
                av[mt][1] = *reinterpret_cast<const uint4*>(&As[(r0 + 8) * GSTRIDE + 8 * t + 4 * half]);
            }
#pragma unroll
            for (int nt = 0; nt < 4; nt++) {
                int rn = nbase + nt * 8 + g;
                bv[nt] = *reinterpret_cast<const uint4*>(&Bs[rn * GSTRIDE + 8 * t + 4 * half]);
            }
#pragma unroll
            for (int ss = 0; ss < 2; ss++) {
#pragma unroll
                for (int mt = 0; mt < 4; mt++) {
                    uint32_t a0 = (ss == 0) ? av[mt][0].x : av[mt][0].z;
                    uint32_t a2 = (ss == 0) ? av[mt][0].y : av[mt][0].w;
                    uint32_t a1 = (ss == 0) ? av[mt][1].x : av[mt][1].z;
                    uint32_t a3 = (ss == 0) ? av[mt][1].y : av[mt][1].w;
#pragma unroll
                    for (int nt = 0; nt < 4; nt++) {
                        uint32_t b0 = (ss == 0) ? bv[nt].x : bv[nt].z;
                        uint32_t b1 = (ss == 0) ? bv[nt].y : bv[nt].w;
                        MMA_TF32(C0[mt][nt][0], C0[mt][nt][1], C0[mt][nt][2], C0[mt][nt][3],
                                 a0, a1, a2, a3, b0, b1);
                    }
                }
            }
        }
        __syncthreads();
    }

#pragma unroll
    for (int mt = 0; mt < 4; mt++) {
        int row0 = bm + mbase + mt * 16 + g;
#pragma unroll
        for (int nt = 0; nt < 4; nt++) {
            int col = bn + nbase + nt * 8 + 2 * t;
            float bx = 0.f, by = 0.f;
            if (bias) { bx = bias[col]; by = bias[col + 1]; }
            float2 o0 = make_float2(C0[mt][nt][0] + bx, C0[mt][nt][1] + by);
            float2 o1 = make_float2(C0[mt][nt][2] + bx, C0[mt][nt][3] + by);
            *reinterpret_cast<float2*>(&C[(size_t)row0 * N + col]) = o0;
            *reinterpret_cast<float2*>(&C[(size_t)(row0 + 8) * N + col]) = o1;
        }
    }
}

// ---------------------------------------------------------------------------
// Axial RoPE in-place on q,k of g_qkv. (unchanged)
// ---------------------------------------------------------------------------
__global__ __launch_bounds__(256) void rope_kernel(float* __restrict__ qkv)
{
    int idx = blockIdx.x * blockDim.x + threadIdx.x;
    const int total = NTOK_ * NH_ * 32;
    if (idx >= total) return;

    int p   = idx & 31;
    int hh  = (idx >> 5) & 7;
    int tok = idx >> 8;
    int sp  = tok & (SEQ_ - 1);
    int i   = sp >> 5;
    int j   = sp & 31;

    float base = (1.0f + (float)(p & 15) * (127.0f / 15.0f)) * PI_F;
    float pos  = (p < 16) ? (-1.0f + (float)i * (2.0f / 31.0f))
                          : (-1.0f + (float)j * (2.0f / 31.0f));
    float th = pos * base;
    float s, c;
    sincosf(th, &s, &c);

    size_t col = (size_t)hh * HD_ + (size_t)p * 2;
    float* q = &qkv[(size_t)tok * QKVN_ + col];
    float* k = q + 512;

    float q0 = q[0], q1 = q[1];
    q[0] = q0 * c - q1 * s;
    q[1] = q1 * c + q0 * s;
    float k0 = k[0], k1 = k[1];
    k[0] = k0 * c - k1 * s;
    k[1] = k1 * c + k0 * s;
}

// ---------------------------------------------------------------------------
// Flash attention on tf32 mma.sync (unchanged from R7).
// ---------------------------------------------------------------------------
__global__ __launch_bounds__(128, 2) void attn_mma(
    const float* __restrict__ qkv, float* __restrict__ outb)
{
    extern __shared__ uint32_t asm_[];
    uint32_t* sQ  = asm_ + A_SQ_OFF;
    uint32_t* sK  = asm_ + A_SK_OFF;
    uint32_t* sP  = asm_ + A_SP_OFF;
    uint32_t* sVt = asm_ + A_SVT_OFF;

    const int bh = blockIdx.y;
    const int bt = bh >> 3;
    const int h  = bh & 7;
    const int q0 = blockIdx.x * 128;
    const int tid = threadIdx.x;
    const int wid = tid >> 5;
    const int lane = tid & 31;
    const int g = lane >> 2;
    const int t = lane & 3;
    const int wq0 = wid * 32;

    const float qscale = 0.125f * LOG2E_F;

    const size_t baseQ = ((size_t)bt * SEQ_ + q0) * QKVN_ + (size_t)h * HD_;
    {
        const int row = tid >> 4;
        const int c4  = (tid & 15) << 2;
#pragma unroll
        for (int it = 0; it < 16; it++) {
            int r = row + it * 8;
            float4 v = *reinterpret_cast<const float4*>(&qkv[baseQ + (size_t)r * QKVN_ + c4]);
            uint4 u = make_uint4(f2tf32(v.x * qscale), f2tf32(v.y * qscale),
                                 f2tf32(v.z * qscale), f2tf32(v.w * qscale));
            *reinterpret_cast<uint4*>(&sQ[r * AQS_ + c4]) = u;
        }
    }

    float O[2][8][4];
    float m_[2][2], l_[2][2];
#pragma unroll
    for (int mt = 0; mt < 2; mt++) {
#pragma unroll
        for (int r = 0; r < 2; r++) { m_[mt][r] = -1e30f; l_[mt][r] = 0.0f; }
#pragma unroll
        for (int nd = 0; nd < 8; nd++)
#pragma unroll
            for (int f = 0; f < 4; f++) O[mt][nd][f] = 0.0f;
    }

    for (int kt = 0; kt < 16; kt++) {
        const size_t baseK = ((size_t)bt * SEQ_ + kt * 64) * QKVN_ + 512 + (size_t)h * HD_;
        const size_t baseV = baseK + 512;

        __syncthreads();
        {
            const int row = tid >> 4;
            const int c4  = (tid & 15) << 2;
#pragma unroll
            for (int it = 0; it < 8; it++) {
                int r = row + it * 8;
                float4 kv = *reinterpret_cast<const float4*>(&qkv[baseK + (size_t)r * QKVN_ + c4]);
                *reinterpret_cast<uint4*>(&sK[r * AQS_ + c4]) =
                    make_uint4(f2tf32(kv.x), f2tf32(kv.y), f2tf32(kv.z), f2tf32(kv.w));
                float4 vv = *reinterpret_cast<const float4*>(&qkv[baseV + (size_t)r * QKVN_ + c4]);
                sVt[(c4 + 0) * AVS_ + r] = f2tf32(vv.x);
                sVt[(c4 + 1) * AVS_ + r] = f2tf32(vv.y);
                sVt[(c4 + 2) * AVS_ + r] = f2tf32(vv.z);
                sVt[(c4 + 3) * AVS_ + r] = f2tf32(vv.w);
            }
        }
        __syncthreads();

        float S[2][8][4];
#pragma unroll
        for (int mt = 0; mt < 2; mt++)
#pragma unroll
            for (int nt = 0; nt < 8; nt++)
#pragma unroll
                for (int f = 0; f < 4; f++) S[mt][nt][f] = 0.0f;

#pragma unroll
        for (int h2 = 0; h2 < 4; h2++) {
            const int koff = 32 * (h2 >> 1) + 4 * (h2 & 1) + 8 * t;
            uint4 av[2][2];
#pragma unroll
            for (int mt = 0; mt < 2; mt++) {
                int r0 = wq0 + 16 * mt + g;
                av[mt][0] = *reinterpret_cast<const uint4*>(&sQ[r0 * AQS_ + koff]);
                av[mt][1] = *reinterpret_cast<const uint4*>(&sQ[(r0 + 8) * AQS_ + koff]);
            }
            uint4 bv[8];
#pragma unroll
            for (int nt = 0; nt < 8; nt++)
                bv[nt] = *reinterpret_cast<const uint4*>(&sK[(8 * nt + g) * AQS_ + koff]);
#pragma unroll
            for (int ss = 0; ss < 2; ss++) {
#pragma unroll
                for (int mt = 0; mt < 2; mt++) {
                    uint32_t a0 = (ss == 0) ? av[mt][0].x : av[mt][0].z;
                    uint32_t a2 = (ss == 0) ? av[mt][0].y : av[mt][0].w;
                    uint32_t a1 = (ss == 0) ? av[mt][1].x : av[mt][1].z;
                    uint32_t a3 = (ss == 0) ? av[mt][1].y : av[mt][1].w;
#pragma unroll
                    for (int nt = 0; nt < 8; nt++) {
                        uint32_t b0 = (ss == 0) ? bv[nt].x : bv[nt].z;
                        uint32_t b1 = (ss == 0) ? bv[nt].y : bv[nt].w;
                        MMA_TF32(S[mt][nt][0], S[mt][nt][1], S[mt][nt][2], S[mt][nt][3],
                                 a0, a1, a2, a3, b0, b1);
                    }
                }
            }
        }

#pragma unroll
        for (int mt = 0; mt < 2; mt++) {
#pragma unroll
            for (int r = 0; r < 2; r++) {
                float mx = -1e30f;
#pragma unroll
                for (int nt = 0; nt < 8; nt++)
                    mx = fmaxf(mx, fmaxf(S[mt][nt][2 * r], S[mt][nt][2 * r + 1]));
                mx = fmaxf(mx, __shfl_xor_sync(0xffffffffu, mx, 1));
                mx = fmaxf(mx, __shfl_xor_sync(0xffffffffu, mx, 2));
                float mo = m_[mt][r];
                float mn = fmaxf(mo, mx);
                float alpha = exp2f(mo - mn);
                float sum = 0.0f;
#pragma unroll
                for (int nt = 0; nt < 8; nt++) {
                    float p0 = exp2f(S[mt][nt][2 * r] - mn);
                    float p1 = exp2f(S[mt][nt][2 * r + 1] - mn);
                    S[mt][nt][2 * r] = p0;
                    S[mt][nt][2 * r + 1] = p1;
                    sum += p0 + p1;
                }
                sum += __shfl_xor_sync(0xffffffffu, sum, 1);
                sum += __shfl_xor_sync(0xffffffffu, sum, 2);
                m_[mt][r] = mn;
                l_[mt][r] = l_[mt][r] * alpha + sum;
#pragma unroll
                for (int nd = 0; nd < 8; nd++) {
                    O[mt][nd][2 * r]     *= alpha;
                    O[mt][nd][2 * r + 1] *= alpha;
                }
            }
        }

#pragma unroll
        for (int mt = 0; mt < 2; mt++) {
            int r0 = wq0 + 16 * mt + g;
#pragma unroll
            for (int nt = 0; nt < 8; nt++) {
                uint2 lo = make_uint2(f2tf32(S[mt][nt][0]), f2tf32(S[mt][nt][1]));
                uint2 hi = make_uint2(f2tf32(S[mt][nt][2]), f2tf32(S[mt][nt][3]));
                *reinterpret_cast<uint2*>(&sP[r0 * AQS_ + 8 * nt + 2 * t]) = lo;
                *reinterpret_cast<uint2*>(&sP[(r0 + 8) * AQS_ + 8 * nt + 2 * t]) = hi;
            }
        }
        __syncwarp();

#pragma unroll
        for (int h2 = 0; h2 < 4; h2++) {
            const int koff = 32 * (h2 >> 1) + 4 * (h2 & 1) + 8 * t;
            uint4 av[2][2];
#pragma unroll
            for (int mt = 0; mt < 2; mt++) {
                int r0 = wq0 + 16 * mt + g;
                av[mt][0] = *reinterpret_cast<const uint4*>(&sP[r0 * AQS_ + koff]);
                av[mt][1] = *reinterpret_cast<const uint4*>(&sP[(r0 + 8) * AQS_ + koff]);
            }
#pragma unroll
            for (int ss = 0; ss < 2; ss++) {
                uint2 bb[8];
#pragma unroll
                for (int nd = 0; nd < 8; nd++)
                    bb[nd] = *reinterpret_cast<const uint2*>(&sVt[(8 * nd + g) * AVS_ + koff + 2 * ss]);
#pragma unroll
                for (int mt = 0; mt < 2; mt++) {
                    uint32_t a0 = (ss == 0) ? av[mt][0].x : av[mt][0].z;
                    uint32_t a2 = (ss == 0) ? av[mt][0].y : av[mt][0].w;
                    uint32_t a1 = (ss == 0) ? av[mt][1].x : av[mt][1].z;
                    uint32_t a3 = (ss == 0) ? av[mt][1].y : av[mt][1].w;
#pragma unroll
                    for (int nd = 0; nd < 8; nd++) {
                        MMA_TF32(O[mt][nd][0], O[mt][nd][1], O[mt][nd][2], O[mt][nd][3],
                                 a0, a1, a2, a3, bb[nd].x, bb[nd].y);
                    }
                }
            }
        }
    }

    // ---- Normalize + write tf32-rounded ----
    const size_t outBase = ((size_t)bt * SEQ_ + q0) * INNER_ + (size_t)h * HD_;
#pragma unroll
    for (int mt = 0; mt < 2; mt++) {
#pragma unroll
        for (int r = 0; r < 2; r++) {
            float inv = 1.0f / l_[mt][r];
            int row = wq0 + 16 * mt + g + 8 * r;
#pragma unroll
            for (int nd = 0; nd < 8; nd++) {
                uint2 o = make_uint2(f2tf32(O[mt][nd][2 * r] * inv),
                                     f2tf32(O[mt][nd][2 * r + 1] * inv));
                *reinterpret_cast<uint2*>(&outb[outBase + (size_t)row * INNER_ + 8 * nd + 2 * t]) = o;
            }
        }
    }
}

// ---------------------------------------------------------------------------
extern "C" void kernel_launch(void* const* d_in, const int* in_sizes, int n_in,
                              void* d_out, int out_size)
{
    const float* x     = (const float*)d_in[0];
    const float* w_qkv = (const float*)d_in[1];
    const float* w_out = (const float*)d_in[2];
    const float* b_out = (const float*)d_in[3];
    float* out = (float*)d_out;

    float* qkv = nullptr; float* attn = nullptr;
    float* xr = nullptr;  float* wq = nullptr;  float* wo = nullptr;
    cudaGetSymbolAddress((void**)&qkv, g_qkv);
    cudaGetSymbolAddress((void**)&attn, g_attn);
    cudaGetSymbolAddress((void**)&xr, g_x);
    cudaGetSymbolAddress((void**)&wq, g_wq);
    cudaGetSymbolAddress((void**)&wo, g_wo);

    static bool attr_set = false;
    if (!attr_set) {
        cudaFuncSetAttribute(gemm_mma,
                             cudaFuncAttributeMaxDynamicSharedMemorySize, GEMM_SMEM_BYTES);
        cudaFuncSetAttribute(attn_mma,
                             cudaFuncAttributeMaxDynamicSharedMemorySize, ATTN_SMEM_BYTES);
        attr_set = true;
    }

    // 0) Round inputs to tf32-in-fp32
    {
        int n4x = NTOK_ * DIM_ / 4;
        round_tf32<<<(n4x + 255) / 256, 256>>>(x, xr, n4x);
        int n4q = QKVN_ * DIM_ / 4;
        round_tf32<<<(n4q + 255) / 256, 256>>>(w_qkv, wq, n4q);
        int n4o = INNER_ * DIM_ / 4;
        round_tf32<<<(n4o + 255) / 256, 256>>>(w_out, wo, n4o);
    }

    // 1) QKV projection
    {
        dim3 grid(QKVN_ / 128, NTOK_ / 128);
        gemm_mma<<<grid, 256, GEMM_SMEM_BYTES>>>(xr, wq, nullptr, qkv, QKVN_);
    }

    // 2) RoPE
    {
        int total = NTOK_ * NH_ * 32;
        rope_kernel<<<(total + 255) / 256, 256>>>(qkv);
    }

    // 3) Attention
    {
        dim3 grid(SEQ_ / 128, BT_ * NH_);
        attn_mma<<<grid, 128, ATTN_SMEM_BYTES>>>(qkv, attn);
    }

    // 4) Output projection + bias
    {
        dim3 grid(INNER_ / 128, NTOK_ / 128);
        gemm_mma<<<grid, 256, GEMM_SMEM_BYTES>>>(attn, wo, b_out, out, INNER_);
    }
}